// round 1
// baseline (speedup 1.0000x reference)
#include <cuda_runtime.h>
#include <cuda_bf16.h>
#include <mma.h>

using namespace nvcuda;

#define NB 8
#define NT 4096
#define NA 64
#define DD 256
#define MTOK (NB*NT)
#define QKVLD 768

// ---------------- scratch (device globals; no allocations allowed) ----------
__device__ __nv_bfloat16 g_xb[MTOK*DD];              // x in bf16
__device__ __nv_bfloat16 g_Wqkv[DD*3*DD];            // W_qkv bf16
__device__ __nv_bfloat16 g_Wfc2[DD*DD];              // W_fc2 bf16
__device__ __nv_bfloat16 g_qkv[(size_t)MTOK*3*DD];   // q|k|v per token, bf16
__device__ __nv_bfloat16 g_qagent[NA*DD];            // scale folded in
__device__ __nv_bfloat16 g_kagent[NA*DD];            // scale folded in
__device__ float        g_S1[NB*NA*NT];              // stage-1 logits
__device__ __nv_bfloat16 g_P1[NB*NA*NT];             // stage-1 probs
__device__ float        g_va0[NB*NA*DD];             // attn1 @ v
__device__ __nv_bfloat16 g_va[NB*NA*DD];             // after fc1, bf16
__device__ __nv_bfloat16 g_mid[MTOK*DD];             // attn2 @ va, bf16

// ---------------- input conversion ------------------------------------------
__global__ void conv_inputs(const float* __restrict__ x,
                            const float* __restrict__ Wqkv,
                            const float* __restrict__ Wfc2) {
    int stride = gridDim.x * blockDim.x;
    int tid = blockIdx.x * blockDim.x + threadIdx.x;
    for (int i = tid; i < MTOK*DD; i += stride)
        g_xb[i] = __float2bfloat16(x[i]);
    for (int i = tid; i < DD*3*DD; i += stride)
        g_Wqkv[i] = __float2bfloat16(Wqkv[i]);
    for (int i = tid; i < DD*DD; i += stride)
        g_Wfc2[i] = __float2bfloat16(Wfc2[i]);
}

// ---------------- agent projection (tiny) -----------------------------------
// ag = agent @ W_agent + b_agent; split into q_agent/k_agent; fold d^-0.5.
__global__ void agent_proj(const float* __restrict__ agent,
                           const float* __restrict__ W,
                           const float* __restrict__ b) {
    __shared__ float arow[DD];
    int a = blockIdx.x;
    for (int i = threadIdx.x; i < DD; i += blockDim.x)
        arow[i] = agent[a*DD + i];
    __syncthreads();
    int o = threadIdx.x;  // 0..511
    float s = 0.f;
    #pragma unroll 8
    for (int d = 0; d < DD; d++)
        s += arow[d] * W[d*2*DD + o];
    s += b[o];
    s *= 0.0625f;  // 256^-0.5
    if (o < DD) g_qagent[a*DD + o]      = __float2bfloat16(s);
    else        g_kagent[a*DD + (o-DD)] = __float2bfloat16(s);
}

// ---------------- qkv GEMM: [32768,256] @ [256,768] + b --------------------
// tile 128x64, 8 warps (4x2), each warp 32x32 via 2x2 wmma frags
__global__ void gemm_qkv(const float* __restrict__ bqkv) {
    __shared__ float stage[128*64];
    int w  = threadIdx.x >> 5;
    int wm = w >> 1, wn = w & 1;
    int row0 = blockIdx.y * 128, col0 = blockIdx.x * 64;

    wmma::fragment<wmma::accumulator,16,16,16,float> acc[2][2];
    #pragma unroll
    for (int i = 0; i < 2; i++)
        #pragma unroll
        for (int j = 0; j < 2; j++) wmma::fill_fragment(acc[i][j], 0.f);

    for (int kk = 0; kk < DD; kk += 16) {
        wmma::fragment<wmma::matrix_a,16,16,16,__nv_bfloat16,wmma::row_major> af[2];
        wmma::fragment<wmma::matrix_b,16,16,16,__nv_bfloat16,wmma::row_major> bf[2];
        #pragma unroll
        for (int i = 0; i < 2; i++)
            wmma::load_matrix_sync(af[i], g_xb + (size_t)(row0 + wm*32 + i*16)*DD + kk, DD);
        #pragma unroll
        for (int j = 0; j < 2; j++)
            wmma::load_matrix_sync(bf[j], g_Wqkv + (size_t)kk*QKVLD + col0 + wn*32 + j*16, QKVLD);
        #pragma unroll
        for (int i = 0; i < 2; i++)
            #pragma unroll
            for (int j = 0; j < 2; j++)
                wmma::mma_sync(acc[i][j], af[i], bf[j], acc[i][j]);
    }
    #pragma unroll
    for (int i = 0; i < 2; i++)
        #pragma unroll
        for (int j = 0; j < 2; j++)
            wmma::store_matrix_sync(stage + (wm*32 + i*16)*64 + wn*32 + j*16,
                                    acc[i][j], 64, wmma::mem_row_major);
    __syncthreads();
    for (int e = threadIdx.x; e < 128*64; e += blockDim.x) {
        int r = e >> 6, c = e & 63;
        g_qkv[(size_t)(row0 + r)*QKVLD + col0 + c] =
            __float2bfloat16(stage[e] + bqkv[col0 + c]);
    }
}

// ---------------- stage-1 logits: S1[b] = q_agent @ k_b^T ------------------
// tile 64x64, 4 warps (2x2)
__global__ void gemm_s1() {
    int b = blockIdx.y;
    int col0 = blockIdx.x * 64;
    int w  = threadIdx.x >> 5;
    int wm = w >> 1, wn = w & 1;
    const __nv_bfloat16* kbase = g_qkv + (size_t)b*NT*QKVLD + DD;  // k at offset 256

    wmma::fragment<wmma::accumulator,16,16,16,float> acc[2][2];
    #pragma unroll
    for (int i = 0; i < 2; i++)
        #pragma unroll
        for (int j = 0; j < 2; j++) wmma::fill_fragment(acc[i][j], 0.f);

    for (int kk = 0; kk < DD; kk += 16) {
        wmma::fragment<wmma::matrix_a,16,16,16,__nv_bfloat16,wmma::row_major> af[2];
        wmma::fragment<wmma::matrix_b,16,16,16,__nv_bfloat16,wmma::col_major> bf[2];
        #pragma unroll
        for (int i = 0; i < 2; i++)
            wmma::load_matrix_sync(af[i], g_qagent + (size_t)(wm*32 + i*16)*DD + kk, DD);
        #pragma unroll
        for (int j = 0; j < 2; j++)
            wmma::load_matrix_sync(bf[j], kbase + (size_t)(col0 + wn*32 + j*16)*QKVLD + kk, QKVLD);
        #pragma unroll
        for (int i = 0; i < 2; i++)
            #pragma unroll
            for (int j = 0; j < 2; j++)
                wmma::mma_sync(acc[i][j], af[i], bf[j], acc[i][j]);
    }
    float* out = g_S1 + (size_t)b*NA*NT;
    #pragma unroll
    for (int i = 0; i < 2; i++)
        #pragma unroll
        for (int j = 0; j < 2; j++)
            wmma::store_matrix_sync(out + (size_t)(wm*32 + i*16)*NT + col0 + wn*32 + j*16,
                                    acc[i][j], NT, wmma::mem_row_major);
}

// ---------------- stage-1 softmax over N=4096 -------------------------------
__global__ void softmax1() {
    int row = blockIdx.x;  // b*NA + a
    const float* s = g_S1 + (size_t)row*NT;
    __nv_bfloat16* p = g_P1 + (size_t)row*NT;
    int t = threadIdx.x;
    __shared__ float red[8];

    float m = -1e30f;
    for (int i = t; i < NT; i += 256) m = fmaxf(m, s[i]);
    #pragma unroll
    for (int o = 16; o; o >>= 1) m = fmaxf(m, __shfl_xor_sync(0xffffffffu, m, o));
    if ((t & 31) == 0) red[t >> 5] = m;
    __syncthreads();
    float gm = red[0];
    #pragma unroll
    for (int i = 1; i < 8; i++) gm = fmaxf(gm, red[i]);
    __syncthreads();

    float sum = 0.f;
    for (int i = t; i < NT; i += 256) sum += __expf(s[i] - gm);
    #pragma unroll
    for (int o = 16; o; o >>= 1) sum += __shfl_xor_sync(0xffffffffu, sum, o);
    if ((t & 31) == 0) red[t >> 5] = sum;
    __syncthreads();
    float gs = 0.f;
    #pragma unroll
    for (int i = 0; i < 8; i++) gs += red[i];
    float inv = 1.f / gs;
    for (int i = t; i < NT; i += 256)
        p[i] = __float2bfloat16(__expf(s[i] - gm) * inv);
}

// ---------------- va0[b] = P1[b] @ v_b : [64,4096]@[4096,256] ---------------
__global__ void gemm_va0() {
    int b = blockIdx.y;
    int col0 = blockIdx.x * 64;
    int w  = threadIdx.x >> 5;
    int wm = w >> 1, wn = w & 1;
    const __nv_bfloat16* pbase = g_P1 + (size_t)b*NA*NT;
    const __nv_bfloat16* vbase = g_qkv + (size_t)b*NT*QKVLD + 2*DD;  // v at 512

    wmma::fragment<wmma::accumulator,16,16,16,float> acc[2][2];
    #pragma unroll
    for (int i = 0; i < 2; i++)
        #pragma unroll
        for (int j = 0; j < 2; j++) wmma::fill_fragment(acc[i][j], 0.f);

    for (int kk = 0; kk < NT; kk += 16) {
        wmma::fragment<wmma::matrix_a,16,16,16,__nv_bfloat16,wmma::row_major> af[2];
        wmma::fragment<wmma::matrix_b,16,16,16,__nv_bfloat16,wmma::row_major> bf[2];
        #pragma unroll
        for (int i = 0; i < 2; i++)
            wmma::load_matrix_sync(af[i], pbase + (size_t)(wm*32 + i*16)*NT + kk, NT);
        #pragma unroll
        for (int j = 0; j < 2; j++)
            wmma::load_matrix_sync(bf[j], vbase + (size_t)kk*QKVLD + col0 + wn*32 + j*16, QKVLD);
        #pragma unroll
        for (int i = 0; i < 2; i++)
            #pragma unroll
            for (int j = 0; j < 2; j++)
                wmma::mma_sync(acc[i][j], af[i], bf[j], acc[i][j]);
    }
    float* out = g_va0 + (size_t)b*NA*DD;
    #pragma unroll
    for (int i = 0; i < 2; i++)
        #pragma unroll
        for (int j = 0; j < 2; j++)
            wmma::store_matrix_sync(out + (size_t)(wm*32 + i*16)*DD + col0 + wn*32 + j*16,
                                    acc[i][j], DD, wmma::mem_row_major);
}

// ---------------- fc1: va = va0 @ W_fc1 + b (tiny, SIMT fp32) ---------------
__global__ void fc1k(const float* __restrict__ W, const float* __restrict__ bias) {
    __shared__ float r0[DD];
    int row = blockIdx.x;  // b*NA + a
    const float* src = g_va0 + (size_t)row*DD;
    for (int i = threadIdx.x; i < DD; i += blockDim.x) r0[i] = src[i];
    __syncthreads();
    int o = threadIdx.x;
    float s = bias[o];
    #pragma unroll 8
    for (int d = 0; d < DD; d++) s += r0[d] * W[d*DD + o];
    g_va[(size_t)row*DD + o] = __float2bfloat16(s);
}

// ---------------- stage 2 fused: logits -> softmax(K=64) -> @ va -----------
// one block per 128 tokens of one batch; 8 warps (4x2)
__global__ void stage2() {
    extern __shared__ char smraw[];
    float* buf1 = (float*)smraw;                                  // 128x64 f32
    __nv_bfloat16* buf2 = (__nv_bfloat16*)(smraw + 128*64*sizeof(float));  // 128x64 bf16

    int b = blockIdx.y, t0 = blockIdx.x * 128;
    int w  = threadIdx.x >> 5;
    int wm = w >> 1, wn = w & 1;

    // --- phase A: logits[128,64] = q_tile @ k_agent^T (scale folded) ---
    {
        wmma::fragment<wmma::accumulator,16,16,16,float> acc[2][2];
        #pragma unroll
        for (int i = 0; i < 2; i++)
            #pragma unroll
            for (int j = 0; j < 2; j++) wmma::fill_fragment(acc[i][j], 0.f);
        const __nv_bfloat16* qbase = g_qkv + (size_t)(b*NT + t0)*QKVLD;  // q at 0
        for (int kk = 0; kk < DD; kk += 16) {
            wmma::fragment<wmma::matrix_a,16,16,16,__nv_bfloat16,wmma::row_major> af[2];
            wmma::fragment<wmma::matrix_b,16,16,16,__nv_bfloat16,wmma::col_major> bf[2];
            #pragma unroll
            for (int i = 0; i < 2; i++)
                wmma::load_matrix_sync(af[i], qbase + (size_t)(wm*32 + i*16)*QKVLD + kk, QKVLD);
            #pragma unroll
            for (int j = 0; j < 2; j++)
                wmma::load_matrix_sync(bf[j], g_kagent + (size_t)(wn*32 + j*16)*DD + kk, DD);
            #pragma unroll
            for (int i = 0; i < 2; i++)
                #pragma unroll
                for (int j = 0; j < 2; j++)
                    wmma::mma_sync(acc[i][j], af[i], bf[j], acc[i][j]);
        }
        #pragma unroll
        for (int i = 0; i < 2; i++)
            #pragma unroll
            for (int j = 0; j < 2; j++)
                wmma::store_matrix_sync(buf1 + (wm*32 + i*16)*64 + wn*32 + j*16,
                                        acc[i][j], 64, wmma::mem_row_major);
    }
    __syncthreads();

    // --- phase B: per-row softmax over 64 agents ---
    if (threadIdx.x < 128) {
        const float* lr = buf1 + threadIdx.x*64;
        float m = -1e30f;
        #pragma unroll 8
        for (int c = 0; c < 64; c++) m = fmaxf(m, lr[c]);
        float sum = 0.f;
        #pragma unroll 8
        for (int c = 0; c < 64; c++) sum += __expf(lr[c] - m);
        float inv = 1.f / sum;
        __nv_bfloat16* pr = buf2 + threadIdx.x*64;
        #pragma unroll 8
        for (int c = 0; c < 64; c++) pr[c] = __float2bfloat16(__expf(lr[c] - m) * inv);
    }

    // --- phase C: mid[128,256] = P2[128,64] @ va_b[64,256], 4 column passes ---
    const __nv_bfloat16* vabase = g_va + (size_t)b*NA*DD;
    for (int nc = 0; nc < 4; nc++) {
        __syncthreads();  // buf2 ready / previous writeout of buf1 done
        wmma::fragment<wmma::accumulator,16,16,16,float> acc[2][2];
        #pragma unroll
        for (int i = 0; i < 2; i++)
            #pragma unroll
            for (int j = 0; j < 2; j++) wmma::fill_fragment(acc[i][j], 0.f);
        for (int kk = 0; kk < 64; kk += 16) {
            wmma::fragment<wmma::matrix_a,16,16,16,__nv_bfloat16,wmma::row_major> af[2];
            wmma::fragment<wmma::matrix_b,16,16,16,__nv_bfloat16,wmma::row_major> bf[2];
            #pragma unroll
            for (int i = 0; i < 2; i++)
                wmma::load_matrix_sync(af[i], buf2 + (wm*32 + i*16)*64 + kk, 64);
            #pragma unroll
            for (int j = 0; j < 2; j++)
                wmma::load_matrix_sync(bf[j], vabase + (size_t)kk*DD + nc*64 + wn*32 + j*16, DD);
            #pragma unroll
            for (int i = 0; i < 2; i++)
                #pragma unroll
                for (int j = 0; j < 2; j++)
                    wmma::mma_sync(acc[i][j], af[i], bf[j], acc[i][j]);
        }
        #pragma unroll
        for (int i = 0; i < 2; i++)
            #pragma unroll
            for (int j = 0; j < 2; j++)
                wmma::store_matrix_sync(buf1 + (wm*32 + i*16)*64 + wn*32 + j*16,
                                        acc[i][j], 64, wmma::mem_row_major);
        __syncthreads();
        for (int e = threadIdx.x; e < 128*64; e += 256) {
            int r = e >> 6, c = e & 63;
            g_mid[(size_t)(b*NT + t0 + r)*DD + nc*64 + c] = __float2bfloat16(buf1[e]);
        }
    }
}

// ---------------- fc2 + bias + residual -> out ------------------------------
__global__ void gemm_fc2(const float* __restrict__ bias,
                         const float* __restrict__ x,
                         float* __restrict__ out) {
    __shared__ float stage[128*64];
    int w  = threadIdx.x >> 5;
    int wm = w >> 1, wn = w & 1;
    int row0 = blockIdx.y * 128, col0 = blockIdx.x * 64;

    wmma::fragment<wmma::accumulator,16,16,16,float> acc[2][2];
    #pragma unroll
    for (int i = 0; i < 2; i++)
        #pragma unroll
        for (int j = 0; j < 2; j++) wmma::fill_fragment(acc[i][j], 0.f);

    for (int kk = 0; kk < DD; kk += 16) {
        wmma::fragment<wmma::matrix_a,16,16,16,__nv_bfloat16,wmma::row_major> af[2];
        wmma::fragment<wmma::matrix_b,16,16,16,__nv_bfloat16,wmma::row_major> bf[2];
        #pragma unroll
        for (int i = 0; i < 2; i++)
            wmma::load_matrix_sync(af[i], g_mid + (size_t)(row0 + wm*32 + i*16)*DD + kk, DD);
        #pragma unroll
        for (int j = 0; j < 2; j++)
            wmma::load_matrix_sync(bf[j], g_Wfc2 + (size_t)kk*DD + col0 + wn*32 + j*16, DD);
        #pragma unroll
        for (int i = 0; i < 2; i++)
            #pragma unroll
            for (int j = 0; j < 2; j++)
                wmma::mma_sync(acc[i][j], af[i], bf[j], acc[i][j]);
    }
    #pragma unroll
    for (int i = 0; i < 2; i++)
        #pragma unroll
        for (int j = 0; j < 2; j++)
            wmma::store_matrix_sync(stage + (wm*32 + i*16)*64 + wn*32 + j*16,
                                    acc[i][j], 64, wmma::mem_row_major);
    __syncthreads();
    for (int e = threadIdx.x; e < 128*64; e += blockDim.x) {
        int r = e >> 6, c = e & 63;
        size_t gi = (size_t)(row0 + r)*DD + col0 + c;
        out[gi] = stage[e] + bias[col0 + c] + x[gi];
    }
}

// ---------------- launcher ---------------------------------------------------
extern "C" void kernel_launch(void* const* d_in, const int* in_sizes, int n_in,
                              void* d_out, int out_size) {
    const float* agent = (const float*)d_in[0];
    const float* x     = (const float*)d_in[1];
    const float* Wqkv  = (const float*)d_in[2];
    const float* bqkv  = (const float*)d_in[3];
    const float* Wag   = (const float*)d_in[4];
    const float* bag   = (const float*)d_in[5];
    const float* Wfc1  = (const float*)d_in[6];
    const float* bfc1  = (const float*)d_in[7];
    const float* Wfc2  = (const float*)d_in[8];
    const float* bfc2  = (const float*)d_in[9];
    float* out = (float*)d_out;

    conv_inputs<<<2048, 256>>>(x, Wqkv, Wfc2);
    agent_proj<<<64, 512>>>(agent, Wag, bag);
    gemm_qkv<<<dim3(12, 256), 256>>>(bqkv);
    gemm_s1<<<dim3(64, 8), 128>>>();
    softmax1<<<512, 256>>>();
    gemm_va0<<<dim3(4, 8), 128>>>();
    fc1k<<<512, 256>>>(Wfc1, bfc1);
    stage2<<<dim3(32, 8), 256, 128*64*(sizeof(float)+sizeof(__nv_bfloat16))>>>();
    gemm_fc2<<<dim3(4, 256), 256>>>(bfc2, x, out);
}

// round 2
// speedup vs baseline: 2.5526x; 2.5526x over previous
#include <cuda_runtime.h>
#include <cuda_bf16.h>
#include <mma.h>

using namespace nvcuda;

#define NB 8
#define NT 4096
#define NA 64
#define DD 256
#define MTOK (NB*NT)
#define QKVLD 768

// ---------------- scratch (device globals; no allocations allowed) ----------
__device__ __nv_bfloat16 g_xb[MTOK*DD];              // x in bf16
__device__ __nv_bfloat16 g_Wqkv[DD*3*DD];            // W_qkv bf16
__device__ __nv_bfloat16 g_Wfc2[DD*DD];              // W_fc2 bf16
__device__ __nv_bfloat16 g_qkv[(size_t)MTOK*3*DD];   // q|k|v per token, bf16
__device__ __nv_bfloat16 g_qagent[NA*DD];            // scale folded in
__device__ __nv_bfloat16 g_kagent[NA*DD];            // scale folded in
__device__ float        g_S1[NB*NA*NT];              // stage-1 logits
__device__ __nv_bfloat16 g_P1[NB*NA*NT];             // stage-1 probs
__device__ float        g_vap[NB*8*NA*DD];           // split-K partials of attn1@v
__device__ __nv_bfloat16 g_va[NB*NA*DD];             // after fc1, bf16
__device__ __nv_bfloat16 g_mid[MTOK*DD];             // attn2 @ va, bf16

// ---------------- input conversion ------------------------------------------
__global__ void conv_inputs(const float* __restrict__ x,
                            const float* __restrict__ Wqkv,
                            const float* __restrict__ Wfc2) {
    int stride = gridDim.x * blockDim.x;
    int tid = blockIdx.x * blockDim.x + threadIdx.x;
    for (int i = tid; i < MTOK*DD; i += stride)
        g_xb[i] = __float2bfloat16(x[i]);
    for (int i = tid; i < DD*3*DD; i += stride)
        g_Wqkv[i] = __float2bfloat16(Wqkv[i]);
    for (int i = tid; i < DD*DD; i += stride)
        g_Wfc2[i] = __float2bfloat16(Wfc2[i]);
}

// ---------------- agent projection (tiny) -----------------------------------
__global__ void agent_proj(const float* __restrict__ agent,
                           const float* __restrict__ W,
                           const float* __restrict__ b) {
    __shared__ float arow[DD];
    int a = blockIdx.x;
    for (int i = threadIdx.x; i < DD; i += blockDim.x)
        arow[i] = agent[a*DD + i];
    __syncthreads();
    int o = threadIdx.x;  // 0..511
    float s = 0.f;
    #pragma unroll 8
    for (int d = 0; d < DD; d++)
        s += arow[d] * W[d*2*DD + o];
    s += b[o];
    s *= 0.0625f;  // 256^-0.5
    if (o < DD) g_qagent[a*DD + o]      = __float2bfloat16(s);
    else        g_kagent[a*DD + (o-DD)] = __float2bfloat16(s);
}

// ---------------- qkv GEMM: [32768,256] @ [256,768] + b --------------------
// tile 128x128, BK=32, double-buffered smem, 8 warps (2x4), warp tile 64x32
__global__ void gemm_qkv(const float* __restrict__ bqkv) {
    __shared__ __nv_bfloat16 As[2][128][40];
    __shared__ __nv_bfloat16 Bs[2][32][136];
    __shared__ float epi[8][16][16];

    int tid = threadIdx.x;
    int w = tid >> 5, lane = tid & 31;
    int wm = w >> 2, wn = w & 3;
    int row0 = blockIdx.y * 128, col0 = blockIdx.x * 128;

    wmma::fragment<wmma::accumulator,16,16,16,float> acc[4][2];
    #pragma unroll
    for (int i = 0; i < 4; i++)
        #pragma unroll
        for (int j = 0; j < 2; j++) wmma::fill_fragment(acc[i][j], 0.f);

    // stage chunk kc into buffer bb
    #define QKV_STAGE(kc, bb) {                                                    \
        _Pragma("unroll")                                                          \
        for (int r = 0; r < 2; r++) {                                              \
            int idx = tid + r*256;                                                 \
            int ar = idx >> 2, ac = (idx & 3) * 8;                                 \
            *(uint4*)(&As[bb][ar][ac]) =                                           \
                *(const uint4*)(g_xb + (size_t)(row0+ar)*DD + (kc) + ac);          \
        }                                                                          \
        _Pragma("unroll")                                                          \
        for (int r = 0; r < 2; r++) {                                              \
            int idx = tid + r*256;                                                 \
            int br = idx >> 4, bc = (idx & 15) * 8;                                \
            *(uint4*)(&Bs[bb][br][bc]) =                                           \
                *(const uint4*)(g_Wqkv + (size_t)((kc)+br)*QKVLD + col0 + bc);     \
        }                                                                          \
    }

    QKV_STAGE(0, 0);
    __syncthreads();
    for (int s = 0; s < 8; s++) {
        if (s < 7) QKV_STAGE((s+1)*32, (s+1)&1);
        int bb = s & 1;
        #pragma unroll
        for (int kk = 0; kk < 2; kk++) {
            wmma::fragment<wmma::matrix_a,16,16,16,__nv_bfloat16,wmma::row_major> af[4];
            wmma::fragment<wmma::matrix_b,16,16,16,__nv_bfloat16,wmma::row_major> bf[2];
            #pragma unroll
            for (int i = 0; i < 4; i++)
                wmma::load_matrix_sync(af[i], &As[bb][wm*64 + i*16][kk*16], 40);
            #pragma unroll
            for (int j = 0; j < 2; j++)
                wmma::load_matrix_sync(bf[j], &Bs[bb][kk*16][wn*32 + j*16], 136);
            #pragma unroll
            for (int i = 0; i < 4; i++)
                #pragma unroll
                for (int j = 0; j < 2; j++)
                    wmma::mma_sync(acc[i][j], af[i], bf[j], acc[i][j]);
        }
        __syncthreads();
    }
    #undef QKV_STAGE

    int r = lane >> 1, c8 = (lane & 1) * 8;
    #pragma unroll
    for (int i = 0; i < 4; i++)
        #pragma unroll
        for (int j = 0; j < 2; j++) {
            wmma::store_matrix_sync(&epi[w][0][0], acc[i][j], 16, wmma::mem_row_major);
            __syncwarp();
            int gr = row0 + wm*64 + i*16 + r;
            int gc = col0 + wn*32 + j*16 + c8;
            __nv_bfloat16 tmp[8];
            #pragma unroll
            for (int e = 0; e < 8; e++)
                tmp[e] = __float2bfloat16(epi[w][r][c8+e] + bqkv[gc+e]);
            *(uint4*)(g_qkv + (size_t)gr*QKVLD + gc) = *(uint4*)tmp;
            __syncwarp();
        }
}

// ---------------- stage-1 logits: S1[b] = q_agent @ k_b^T ------------------
// tile 64x128 (M=agents, N=tokens), BK=32, 8 warps (2x4), warp 32x32
__global__ void gemm_s1() {
    __shared__ __nv_bfloat16 Qa[2][64][40];
    __shared__ __nv_bfloat16 Ks[2][128][40];
    __shared__ float epi[8][16][16];

    int b = blockIdx.y;
    int col0 = blockIdx.x * 128;
    int tid = threadIdx.x;
    int w = tid >> 5, lane = tid & 31;
    int wm = w >> 2, wn = w & 3;

    wmma::fragment<wmma::accumulator,16,16,16,float> acc[2][2];
    #pragma unroll
    for (int i = 0; i < 2; i++)
        #pragma unroll
        for (int j = 0; j < 2; j++) wmma::fill_fragment(acc[i][j], 0.f);

    #define S1_STAGE(kc, bb) {                                                     \
        {   int ar = tid >> 2, ac = (tid & 3) * 8;                                 \
            *(uint4*)(&Qa[bb][ar][ac]) =                                           \
                *(const uint4*)(g_qagent + (size_t)ar*DD + (kc) + ac); }           \
        _Pragma("unroll")                                                          \
        for (int r = 0; r < 2; r++) {                                              \
            int idx = tid + r*256;                                                 \
            int kr = idx >> 2, kcc = (idx & 3) * 8;                                \
            *(uint4*)(&Ks[bb][kr][kcc]) =                                          \
                *(const uint4*)(g_qkv + (size_t)(b*NT + col0 + kr)*QKVLD + DD + (kc) + kcc); \
        }                                                                          \
    }

    S1_STAGE(0, 0);
    __syncthreads();
    for (int s = 0; s < 8; s++) {
        if (s < 7) S1_STAGE((s+1)*32, (s+1)&1);
        int bb = s & 1;
        #pragma unroll
        for (int kk = 0; kk < 2; kk++) {
            wmma::fragment<wmma::matrix_a,16,16,16,__nv_bfloat16,wmma::row_major> af[2];
            wmma::fragment<wmma::matrix_b,16,16,16,__nv_bfloat16,wmma::col_major> bf[2];
            #pragma unroll
            for (int i = 0; i < 2; i++)
                wmma::load_matrix_sync(af[i], &Qa[bb][wm*32 + i*16][kk*16], 40);
            #pragma unroll
            for (int j = 0; j < 2; j++)
                wmma::load_matrix_sync(bf[j], &Ks[bb][wn*32 + j*16][kk*16], 40);
            #pragma unroll
            for (int i = 0; i < 2; i++)
                #pragma unroll
                for (int j = 0; j < 2; j++)
                    wmma::mma_sync(acc[i][j], af[i], bf[j], acc[i][j]);
        }
        __syncthreads();
    }
    #undef S1_STAGE

    float* outb = g_S1 + (size_t)b*NA*NT;
    #pragma unroll
    for (int i = 0; i < 2; i++)
        #pragma unroll
        for (int j = 0; j < 2; j++) {
            wmma::store_matrix_sync(&epi[w][0][0], acc[i][j], 16, wmma::mem_row_major);
            __syncwarp();
            #pragma unroll
            for (int e = 0; e < 2; e++) {
                int idx2 = lane + e*32;
                int r = idx2 >> 2, c4 = (idx2 & 3) * 4;
                int ga = wm*32 + i*16 + r;
                int gt = col0 + wn*32 + j*16 + c4;
                *(float4*)(outb + (size_t)ga*NT + gt) = *(float4*)(&epi[w][r][c4]);
            }
            __syncwarp();
        }
}

// ---------------- stage-1 softmax over N=4096 -------------------------------
__global__ void softmax1() {
    int row = blockIdx.x;
    const float* s = g_S1 + (size_t)row*NT;
    __nv_bfloat16* p = g_P1 + (size_t)row*NT;
    int t = threadIdx.x;
    __shared__ float red[8];

    float m = -1e30f;
    for (int i = t; i < NT; i += 256) m = fmaxf(m, s[i]);
    #pragma unroll
    for (int o = 16; o; o >>= 1) m = fmaxf(m, __shfl_xor_sync(0xffffffffu, m, o));
    if ((t & 31) == 0) red[t >> 5] = m;
    __syncthreads();
    float gm = red[0];
    #pragma unroll
    for (int i = 1; i < 8; i++) gm = fmaxf(gm, red[i]);
    __syncthreads();

    float sum = 0.f;
    for (int i = t; i < NT; i += 256) sum += __expf(s[i] - gm);
    #pragma unroll
    for (int o = 16; o; o >>= 1) sum += __shfl_xor_sync(0xffffffffu, sum, o);
    if ((t & 31) == 0) red[t >> 5] = sum;
    __syncthreads();
    float gs = 0.f;
    #pragma unroll
    for (int i = 0; i < 8; i++) gs += red[i];
    float inv = 1.f / gs;
    for (int i = t; i < NT; i += 256)
        p[i] = __float2bfloat16(__expf(s[i] - gm) * inv);
}

// ---------------- va partials: split-K over tokens ---------------------------
// grid (8 splits, 8 batches), out partial [64,256] per block
__global__ void gemm_va0() {
    __shared__ __align__(16) char smva[44032];
    __nv_bfloat16 (*Ps)[64][40]  = ( __nv_bfloat16(*)[64][40])  smva;          // 10240
    __nv_bfloat16 (*Vs)[32][264] = ( __nv_bfloat16(*)[32][264])(smva + 10240); // 33792
    float (*epi)[16][16]         = ( float(*)[16][16])          smva;          // reuse Ps

    int split = blockIdx.x, b = blockIdx.y;
    int tok0 = split * 512;
    int tid = threadIdx.x;
    int w = tid >> 5, lane = tid & 31;
    int wm = w >> 2, wn = w & 3;   // wm 0..1 (M32), wn 0..3 (N64)

    wmma::fragment<wmma::accumulator,16,16,16,float> acc[2][4];
    #pragma unroll
    for (int i = 0; i < 2; i++)
        #pragma unroll
        for (int j = 0; j < 4; j++) wmma::fill_fragment(acc[i][j], 0.f);

    #define VA_STAGE(kc, bb) {                                                     \
        {   int pr = tid >> 2, pc = (tid & 3) * 8;                                 \
            *(uint4*)(&Ps[bb][pr][pc]) =                                           \
                *(const uint4*)(g_P1 + (size_t)b*NA*NT + (size_t)pr*NT + tok0 + (kc) + pc); } \
        _Pragma("unroll")                                                          \
        for (int r = 0; r < 4; r++) {                                              \
            int idx = tid + r*256;                                                 \
            int vr = idx >> 5, vc = (idx & 31) * 8;                                \
            *(uint4*)(&Vs[bb][vr][vc]) =                                           \
                *(const uint4*)(g_qkv + (size_t)(b*NT + tok0 + (kc) + vr)*QKVLD + 2*DD + vc); \
        }                                                                          \
    }

    VA_STAGE(0, 0);
    __syncthreads();
    for (int s = 0; s < 16; s++) {
        if (s < 15) VA_STAGE((s+1)*32, (s+1)&1);
        int bb = s & 1;
        #pragma unroll
        for (int kk = 0; kk < 2; kk++) {
            wmma::fragment<wmma::matrix_a,16,16,16,__nv_bfloat16,wmma::row_major> af[2];
            wmma::fragment<wmma::matrix_b,16,16,16,__nv_bfloat16,wmma::row_major> bf[4];
            #pragma unroll
            for (int i = 0; i < 2; i++)
                wmma::load_matrix_sync(af[i], &Ps[bb][wm*32 + i*16][kk*16], 40);
            #pragma unroll
            for (int j = 0; j < 4; j++)
                wmma::load_matrix_sync(bf[j], &Vs[bb][kk*16][wn*64 + j*16], 264);
            #pragma unroll
            for (int i = 0; i < 2; i++)
                #pragma unroll
                for (int j = 0; j < 4; j++)
                    wmma::mma_sync(acc[i][j], af[i], bf[j], acc[i][j]);
        }
        __syncthreads();
    }
    #undef VA_STAGE

    float* outb = g_vap + (size_t)(b*8 + split)*NA*DD;
    #pragma unroll
    for (int i = 0; i < 2; i++)
        #pragma unroll
        for (int j = 0; j < 4; j++) {
            wmma::store_matrix_sync(&epi[w][0][0], acc[i][j], 16, wmma::mem_row_major);
            __syncwarp();
            #pragma unroll
            for (int e = 0; e < 2; e++) {
                int idx2 = lane + e*32;
                int r = idx2 >> 2, c4 = (idx2 & 3) * 4;
                int ga = wm*32 + i*16 + r;
                int gd = wn*64 + j*16 + c4;
                *(float4*)(outb + (size_t)ga*DD + gd) = *(float4*)(&epi[w][r][c4]);
            }
            __syncwarp();
        }
}

// ---------------- fc1: sum partials, then va = va0 @ W_fc1 + b --------------
__global__ void fc1k(const float* __restrict__ W, const float* __restrict__ bias) {
    __shared__ float r0[DD];
    int row = blockIdx.x;  // b*NA + a
    int b = row >> 6, a = row & 63;
    int i = threadIdx.x;   // 256 threads, one dim each
    float acc = 0.f;
    #pragma unroll
    for (int sp = 0; sp < 8; sp++)
        acc += g_vap[(size_t)(b*8 + sp)*NA*DD + (size_t)a*DD + i];
    r0[i] = acc;
    __syncthreads();
    int o = threadIdx.x;
    float s = bias[o];
    #pragma unroll 8
    for (int d = 0; d < DD; d++) s += r0[d] * W[d*DD + o];
    g_va[(size_t)row*DD + o] = __float2bfloat16(s);
}

// ---------------- stage 2: logits -> softmax(K=64) -> @ va ------------------
// per block: 128 tokens of one batch. Dynamic smem 99328B.
__global__ void stage2() {
    extern __shared__ __align__(16) char sm2[];
    __nv_bfloat16 (*Qs)[128][40] = ( __nv_bfloat16(*)[128][40]) sm2;             // 20480
    __nv_bfloat16 (*Ka)[64][40]  = ( __nv_bfloat16(*)[64][40]) (sm2 + 20480);    // 10240
    float* logits                = ( float*)                   (sm2 + 30720);    // 128*68*4 = 34816
    __nv_bfloat16 (*Vs)[264]     = ( __nv_bfloat16(*)[264])    (sm2 + 65536);    // 64*264*2 = 33792
    __nv_bfloat16 (*Pm)[72]      = ( __nv_bfloat16(*)[72])     sm2;              // reuse Qs, 18432
    float (*epi)[16][16]         = ( float(*)[16][16])         (sm2 + 20480);    // reuse Ka

    int b = blockIdx.y, t0 = blockIdx.x * 128;
    int tid = threadIdx.x;
    int w = tid >> 5, lane = tid & 31;

    // prefetch va tile [64,256] into Vs (consumed in phase C)
    #pragma unroll
    for (int r = 0; r < 8; r++) {
        int idx = tid + r*256;
        int vr = idx >> 5, vc = (idx & 31) * 8;
        *(uint4*)(&Vs[vr][vc]) =
            *(const uint4*)(g_va + (size_t)(b*NA + vr)*DD + vc);
    }

    // --- phase A: logits[128,64] = q_tile @ ka^T, warps 4x2, warp 32x32 ---
    {
        int wm = w >> 1, wn = w & 1;
        wmma::fragment<wmma::accumulator,16,16,16,float> acc[2][2];
        #pragma unroll
        for (int i = 0; i < 2; i++)
            #pragma unroll
            for (int j = 0; j < 2; j++) wmma::fill_fragment(acc[i][j], 0.f);

        #define S2_STAGE(kc, bb) {                                                 \
            _Pragma("unroll")                                                      \
            for (int r = 0; r < 2; r++) {                                          \
                int idx = tid + r*256;                                             \
                int qr = idx >> 2, qc = (idx & 3) * 8;                             \
                *(uint4*)(&Qs[bb][qr][qc]) =                                       \
                    *(const uint4*)(g_qkv + (size_t)(b*NT + t0 + qr)*QKVLD + (kc) + qc); \
            }                                                                      \
            {   int ar = tid >> 2, ac = (tid & 3) * 8;                             \
                *(uint4*)(&Ka[bb][ar][ac]) =                                       \
                    *(const uint4*)(g_kagent + (size_t)ar*DD + (kc) + ac); }       \
        }

        S2_STAGE(0, 0);
        __syncthreads();
        for (int s = 0; s < 8; s++) {
            if (s < 7) S2_STAGE((s+1)*32, (s+1)&1);
            int bb = s & 1;
            #pragma unroll
            for (int kk = 0; kk < 2; kk++) {
                wmma::fragment<wmma::matrix_a,16,16,16,__nv_bfloat16,wmma::row_major> af[2];
                wmma::fragment<wmma::matrix_b,16,16,16,__nv_bfloat16,wmma::col_major> bf[2];
                #pragma unroll
                for (int i = 0; i < 2; i++)
                    wmma::load_matrix_sync(af[i], &Qs[bb][wm*32 + i*16][kk*16], 40);
                #pragma unroll
                for (int j = 0; j < 2; j++)
                    wmma::load_matrix_sync(bf[j], &Ka[bb][wn*32 + j*16][kk*16], 40);
                #pragma unroll
                for (int i = 0; i < 2; i++)
                    #pragma unroll
                    for (int j = 0; j < 2; j++)
                        wmma::mma_sync(acc[i][j], af[i], bf[j], acc[i][j]);
            }
            __syncthreads();
        }
        #undef S2_STAGE
        #pragma unroll
        for (int i = 0; i < 2; i++)
            #pragma unroll
            for (int j = 0; j < 2; j++)
                wmma::store_matrix_sync(logits + (wm*32 + i*16)*68 + wn*32 + j*16,
                                        acc[i][j], 68, wmma::mem_row_major);
    }
    __syncthreads();

    // --- phase B: per-row softmax over 64 agents -> Pm (bf16, ld 72) ---
    if (tid < 128) {
        const float* lr = logits + tid*68;
        float m = -1e30f;
        #pragma unroll 8
        for (int c = 0; c < 64; c++) m = fmaxf(m, lr[c]);
        float sum = 0.f;
        #pragma unroll 8
        for (int c = 0; c < 64; c++) sum += __expf(lr[c] - m);
        float inv = 1.f / sum;
        #pragma unroll 8
        for (int c = 0; c < 64; c++)
            Pm[tid][c] = __float2bfloat16(__expf(lr[c] - m) * inv);
    }
    __syncthreads();

    // --- phase C: mid[128,256] = Pm[128,64] @ Vs[64,256]; two N passes ---
    {
        int wm = w >> 1, wn = w & 1;   // warp tile 32x64 per pass
        for (int nc = 0; nc < 2; nc++) {
            wmma::fragment<wmma::accumulator,16,16,16,float> acc[2][4];
            #pragma unroll
            for (int i = 0; i < 2; i++)
                #pragma unroll
                for (int j = 0; j < 4; j++) wmma::fill_fragment(acc[i][j], 0.f);
            #pragma unroll
            for (int kk = 0; kk < 4; kk++) {
                wmma::fragment<wmma::matrix_a,16,16,16,__nv_bfloat16,wmma::row_major> af[2];
                wmma::fragment<wmma::matrix_b,16,16,16,__nv_bfloat16,wmma::row_major> bf[4];
                #pragma unroll
                for (int i = 0; i < 2; i++)
                    wmma::load_matrix_sync(af[i], &Pm[wm*32 + i*16][kk*16], 72);
                #pragma unroll
                for (int j = 0; j < 4; j++)
                    wmma::load_matrix_sync(bf[j], &Vs[kk*16][nc*128 + wn*64 + j*16], 264);
                #pragma unroll
                for (int i = 0; i < 2; i++)
                    #pragma unroll
                    for (int j = 0; j < 4; j++)
                        wmma::mma_sync(acc[i][j], af[i], bf[j], acc[i][j]);
            }
            int r = lane >> 1, c8 = (lane & 1) * 8;
            #pragma unroll
            for (int i = 0; i < 2; i++)
                #pragma unroll
                for (int j = 0; j < 4; j++) {
                    wmma::store_matrix_sync(&epi[w][0][0], acc[i][j], 16, wmma::mem_row_major);
                    __syncwarp();
                    int grow = t0 + wm*32 + i*16 + r;
                    int gcol = nc*128 + wn*64 + j*16 + c8;
                    __nv_bfloat16 tmp[8];
                    #pragma unroll
                    for (int e = 0; e < 8; e++)
                        tmp[e] = __float2bfloat16(epi[w][r][c8+e]);
                    *(uint4*)(g_mid + (size_t)(b*NT + grow)*DD + gcol) = *(uint4*)tmp;
                    __syncwarp();
                }
        }
    }
}

// ---------------- fc2 + bias + residual -> out ------------------------------
// tile 128x128, like gemm_qkv but B stride 256, f32 out with residual
__global__ void gemm_fc2(const float* __restrict__ bias,
                         const float* __restrict__ x,
                         float* __restrict__ out) {
    __shared__ __nv_bfloat16 As[2][128][40];
    __shared__ __nv_bfloat16 Bs[2][32][136];
    __shared__ float epi[8][16][16];

    int tid = threadIdx.x;
    int w = tid >> 5, lane = tid & 31;
    int wm = w >> 2, wn = w & 3;
    int row0 = blockIdx.y * 128, col0 = blockIdx.x * 128;

    wmma::fragment<wmma::accumulator,16,16,16,float> acc[4][2];
    #pragma unroll
    for (int i = 0; i < 4; i++)
        #pragma unroll
        for (int j = 0; j < 2; j++) wmma::fill_fragment(acc[i][j], 0.f);

    #define FC2_STAGE(kc, bb) {                                                    \
        _Pragma("unroll")                                                          \
        for (int r = 0; r < 2; r++) {                                              \
            int idx = tid + r*256;                                                 \
            int ar = idx >> 2, ac = (idx & 3) * 8;                                 \
            *(uint4*)(&As[bb][ar][ac]) =                                           \
                *(const uint4*)(g_mid + (size_t)(row0+ar)*DD + (kc) + ac);         \
        }                                                                          \
        _Pragma("unroll")                                                          \
        for (int r = 0; r < 2; r++) {                                              \
            int idx = tid + r*256;                                                 \
            int br = idx >> 4, bc = (idx & 15) * 8;                                \
            *(uint4*)(&Bs[bb][br][bc]) =                                           \
                *(const uint4*)(g_Wfc2 + (size_t)((kc)+br)*DD + col0 + bc);        \
        }                                                                          \
    }

    FC2_STAGE(0, 0);
    __syncthreads();
    for (int s = 0; s < 8; s++) {
        if (s < 7) FC2_STAGE((s+1)*32, (s+1)&1);
        int bb = s & 1;
        #pragma unroll
        for (int kk = 0; kk < 2; kk++) {
            wmma::fragment<wmma::matrix_a,16,16,16,__nv_bfloat16,wmma::row_major> af[4];
            wmma::fragment<wmma::matrix_b,16,16,16,__nv_bfloat16,wmma::row_major> bf[2];
            #pragma unroll
            for (int i = 0; i < 4; i++)
                wmma::load_matrix_sync(af[i], &As[bb][wm*64 + i*16][kk*16], 40);
            #pragma unroll
            for (int j = 0; j < 2; j++)
                wmma::load_matrix_sync(bf[j], &Bs[bb][kk*16][wn*32 + j*16], 136);
            #pragma unroll
            for (int i = 0; i < 4; i++)
                #pragma unroll
                for (int j = 0; j < 2; j++)
                    wmma::mma_sync(acc[i][j], af[i], bf[j], acc[i][j]);
        }
        __syncthreads();
    }
    #undef FC2_STAGE

    int r = lane >> 1, c8 = (lane & 1) * 8;
    #pragma unroll
    for (int i = 0; i < 4; i++)
        #pragma unroll
        for (int j = 0; j < 2; j++) {
            wmma::store_matrix_sync(&epi[w][0][0], acc[i][j], 16, wmma::mem_row_major);
            __syncwarp();
            int gr = row0 + wm*64 + i*16 + r;
            int gc = col0 + wn*32 + j*16 + c8;
            size_t gi = (size_t)gr*DD + gc;
            float o0[4], o1[4];
            #pragma unroll
            for (int e = 0; e < 4; e++) o0[e] = epi[w][r][c8+e]   + bias[gc+e]   + x[gi+e];
            #pragma unroll
            for (int e = 0; e < 4; e++) o1[e] = epi[w][r][c8+4+e] + bias[gc+4+e] + x[gi+4+e];
            *(float4*)(out + gi)     = *(float4*)o0;
            *(float4*)(out + gi + 4) = *(float4*)o1;
            __syncwarp();
        }
}

// ---------------- launcher ---------------------------------------------------
extern "C" void kernel_launch(void* const* d_in, const int* in_sizes, int n_in,
                              void* d_out, int out_size) {
    const float* agent = (const float*)d_in[0];
    const float* x     = (const float*)d_in[1];
    const float* Wqkv  = (const float*)d_in[2];
    const float* bqkv  = (const float*)d_in[3];
    const float* Wag   = (const float*)d_in[4];
    const float* bag   = (const float*)d_in[5];
    const float* Wfc1  = (const float*)d_in[6];
    const float* bfc1  = (const float*)d_in[7];
    const float* Wfc2  = (const float*)d_in[8];
    const float* bfc2  = (const float*)d_in[9];
    float* out = (float*)d_out;

    static bool attr_done = false;
    if (!attr_done) {
        cudaFuncSetAttribute(stage2, cudaFuncAttributeMaxDynamicSharedMemorySize, 99328);
        attr_done = true;
    }

    conv_inputs<<<2048, 256>>>(x, Wqkv, Wfc2);
    agent_proj<<<64, 512>>>(agent, Wag, bag);
    gemm_qkv<<<dim3(6, 256), 256>>>(bqkv);
    gemm_s1<<<dim3(32, 8), 256>>>();
    softmax1<<<512, 256>>>();
    gemm_va0<<<dim3(8, 8), 256>>>();
    fc1k<<<512, 256>>>(Wfc1, bfc1);
    stage2<<<dim3(32, 8), 256, 99328>>>();
    gemm_fc2<<<dim3(2, 256), 256>>>(bfc2, x, out);
}

// round 4
// speedup vs baseline: 2.8015x; 1.0975x over previous
#include <cuda_runtime.h>
#include <cuda_bf16.h>
#include <mma.h>
#include <cstdint>

using namespace nvcuda;

#define NB 8
#define NT 4096
#define NA 64
#define DD 256
#define MTOK (NB*NT)
#define QKVLD 768

// ---------------- scratch (device globals; no allocations allowed) ----------
__device__ __nv_bfloat16 g_xb[MTOK*DD];              // x in bf16
__device__ __nv_bfloat16 g_Wqkv[DD*3*DD];            // W_qkv bf16 [K,N]
__device__ __nv_bfloat16 g_Wfc2[DD*DD];              // W_fc2 bf16 [K,N]
__device__ __nv_bfloat16 g_qkv[(size_t)MTOK*3*DD];   // q|k|v per token, bf16
__device__ __nv_bfloat16 g_qagent[NA*DD];            // scale folded in
__device__ __nv_bfloat16 g_kagent[NA*DD];            // scale folded in
__device__ float        g_S1[NB*NA*NT];              // stage-1 logits
__device__ __nv_bfloat16 g_P1[NB*NA*NT];             // stage-1 probs
__device__ float        g_vap[NB*8*NA*DD];           // split-K partials of attn1@v
__device__ __nv_bfloat16 g_va[NB*NA*DD];             // after fc1, bf16
__device__ __nv_bfloat16 g_mid[MTOK*DD];             // attn2 @ va, bf16

// ---------------- cp.async helpers ------------------------------------------
__device__ __forceinline__ uint32_t smem_u32(const void* p) {
    uint32_t a;
    asm("{ .reg .u64 t; cvta.to.shared.u64 t, %1; cvt.u32.u64 %0, t; }" : "=r"(a) : "l"(p));
    return a;
}
#define CPA16(s, g)  asm volatile("cp.async.cg.shared.global [%0], [%1], 16;" :: "r"(s), "l"(g))
#define CPA_COMMIT() asm volatile("cp.async.commit_group;" ::: "memory")
#define CPA_WAIT(n)  asm volatile("cp.async.wait_group %0;" :: "n"(n) : "memory")

// ---------------- input conversion ------------------------------------------
__global__ void conv_inputs(const float* __restrict__ x,
                            const float* __restrict__ Wqkv,
                            const float* __restrict__ Wfc2) {
    int stride = gridDim.x * blockDim.x;
    int tid = blockIdx.x * blockDim.x + threadIdx.x;
    for (int i = tid; i < MTOK*DD; i += stride)
        g_xb[i] = __float2bfloat16(x[i]);
    for (int i = tid; i < DD*3*DD; i += stride)
        g_Wqkv[i] = __float2bfloat16(Wqkv[i]);
    for (int i = tid; i < DD*DD; i += stride)
        g_Wfc2[i] = __float2bfloat16(Wfc2[i]);
}

// ---------------- agent projection (tiny) -----------------------------------
__global__ void agent_proj(const float* __restrict__ agent,
                           const float* __restrict__ W,
                           const float* __restrict__ b) {
    __shared__ float arow[DD];
    int a = blockIdx.x;
    for (int i = threadIdx.x; i < DD; i += blockDim.x)
        arow[i] = agent[a*DD + i];
    __syncthreads();
    int o = threadIdx.x;  // 0..511
    float s = 0.f;
    #pragma unroll 8
    for (int d = 0; d < DD; d++)
        s += arow[d] * W[d*2*DD + o];
    s += b[o];
    s *= 0.0625f;  // 256^-0.5
    if (o < DD) g_qagent[a*DD + o]      = __float2bfloat16(s);
    else        g_kagent[a*DD + (o-DD)] = __float2bfloat16(s);
}

// ---------------- qkv GEMM: [32768,256] @ [256,768] + b --------------------
// tile 128x128, BK=32, 3-stage cp.async pipeline, 8 warps (2x4), warp 64x32
// dynamic smem: As 3x10240 | Bs 3x8704 = 56832; epilogue reuses As region
__global__ void __launch_bounds__(256) gemm_qkv(const float* __restrict__ bqkv) {
    extern __shared__ __align__(16) char smq[];
    __nv_bfloat16 (*As)[128][40] = (__nv_bfloat16(*)[128][40]) smq;
    __nv_bfloat16 (*Bs)[32][136] = (__nv_bfloat16(*)[32][136])(smq + 30720);
    float (*epi)[16][16]         = (float(*)[16][16])          smq;
    uint32_t sA = smem_u32(smq), sB = sA + 30720u;

    int tid = threadIdx.x;
    int w = tid >> 5, lane = tid & 31;
    int wm = w >> 2, wn = w & 3;
    int row0 = blockIdx.y * 128, col0 = blockIdx.x * 128;

    wmma::fragment<wmma::accumulator,16,16,16,float> acc[4][2];
    #pragma unroll
    for (int i = 0; i < 4; i++)
        #pragma unroll
        for (int j = 0; j < 2; j++) wmma::fill_fragment(acc[i][j], 0.f);

    #define QKV_STAGE(kc, bb) {                                                    \
        _Pragma("unroll")                                                          \
        for (int r = 0; r < 2; r++) {                                              \
            int idx = tid + r*256;                                                 \
            int ar = idx >> 2, ac = (idx & 3) * 8;                                 \
            CPA16(sA + (uint32_t)(bb)*10240u + (uint32_t)ar*80u + (uint32_t)ac*2u, \
                  g_xb + (size_t)(row0+ar)*DD + (kc) + ac);                        \
        }                                                                          \
        _Pragma("unroll")                                                          \
        for (int r = 0; r < 2; r++) {                                              \
            int idx = tid + r*256;                                                 \
            int br = idx >> 4, bc = (idx & 15) * 8;                                \
            CPA16(sB + (uint32_t)(bb)*8704u + (uint32_t)br*272u + (uint32_t)bc*2u, \
                  g_Wqkv + (size_t)((kc)+br)*QKVLD + col0 + bc);                   \
        }                                                                          \
        CPA_COMMIT(); }

    QKV_STAGE(0, 0);
    QKV_STAGE(32, 1);
    for (int s = 0; s < 8; s++) {
        if (s < 6) QKV_STAGE((s+2)*32, (s+2)%3);
        if (s < 6)      { CPA_WAIT(2); }
        else if (s == 6){ CPA_WAIT(1); }
        else            { CPA_WAIT(0); }
        __syncthreads();
        int bb = s % 3;
        #pragma unroll
        for (int kk = 0; kk < 2; kk++) {
            wmma::fragment<wmma::matrix_a,16,16,16,__nv_bfloat16,wmma::row_major> af[4];
            wmma::fragment<wmma::matrix_b,16,16,16,__nv_bfloat16,wmma::row_major> bf[2];
            #pragma unroll
            for (int i = 0; i < 4; i++)
                wmma::load_matrix_sync(af[i], &As[bb][wm*64 + i*16][kk*16], 40);
            #pragma unroll
            for (int j = 0; j < 2; j++)
                wmma::load_matrix_sync(bf[j], &Bs[bb][kk*16][wn*32 + j*16], 136);
            #pragma unroll
            for (int i = 0; i < 4; i++)
                #pragma unroll
                for (int j = 0; j < 2; j++)
                    wmma::mma_sync(acc[i][j], af[i], bf[j], acc[i][j]);
        }
        __syncthreads();
    }
    #undef QKV_STAGE

    int r = lane >> 1, c8 = (lane & 1) * 8;
    #pragma unroll
    for (int i = 0; i < 4; i++)
        #pragma unroll
        for (int j = 0; j < 2; j++) {
            wmma::store_matrix_sync(&epi[w][0][0], acc[i][j], 16, wmma::mem_row_major);
            __syncwarp();
            int gr = row0 + wm*64 + i*16 + r;
            int gc = col0 + wn*32 + j*16 + c8;
            __nv_bfloat16 tmp[8];
            #pragma unroll
            for (int e = 0; e < 8; e++)
                tmp[e] = __float2bfloat16(epi[w][r][c8+e] + bqkv[gc+e]);
            *(uint4*)(g_qkv + (size_t)gr*QKVLD + gc) = *(uint4*)tmp;
            __syncwarp();
        }
}

// ---------------- stage-1 logits: S1[b] = q_agent @ k_b^T ------------------
// tile 64x128, BK=32, 2-stage cp.async, 8 warps (2x4), warp 32x32
__global__ void __launch_bounds__(256) gemm_s1() {
    __shared__ __nv_bfloat16 Qa[2][64][40];
    __shared__ __nv_bfloat16 Ks[2][128][40];
    __shared__ float epi[8][16][16];
    uint32_t sQ = smem_u32(&Qa[0][0][0]);
    uint32_t sK = smem_u32(&Ks[0][0][0]);

    int b = blockIdx.y;
    int col0 = blockIdx.x * 128;
    int tid = threadIdx.x;
    int w = tid >> 5, lane = tid & 31;
    int wm = w >> 2, wn = w & 3;

    wmma::fragment<wmma::accumulator,16,16,16,float> acc[2][2];
    #pragma unroll
    for (int i = 0; i < 2; i++)
        #pragma unroll
        for (int j = 0; j < 2; j++) wmma::fill_fragment(acc[i][j], 0.f);

    #define S1_STAGE(kc, bb) {                                                     \
        {   int ar = tid >> 2, ac = (tid & 3) * 8;                                 \
            CPA16(sQ + (uint32_t)(bb)*5120u + (uint32_t)ar*80u + (uint32_t)ac*2u,  \
                  g_qagent + (size_t)ar*DD + (kc) + ac); }                         \
        _Pragma("unroll")                                                          \
        for (int r = 0; r < 2; r++) {                                              \
            int idx = tid + r*256;                                                 \
            int kr = idx >> 2, kcc = (idx & 3) * 8;                                \
            CPA16(sK + (uint32_t)(bb)*10240u + (uint32_t)kr*80u + (uint32_t)kcc*2u,\
                  g_qkv + (size_t)(b*NT + col0 + kr)*QKVLD + DD + (kc) + kcc);     \
        }                                                                          \
        CPA_COMMIT(); }

    S1_STAGE(0, 0);
    for (int s = 0; s < 8; s++) {
        if (s < 7) S1_STAGE((s+1)*32, (s+1)&1);
        if (s < 7) { CPA_WAIT(1); } else { CPA_WAIT(0); }
        __syncthreads();
        int bb = s & 1;
        #pragma unroll
        for (int kk = 0; kk < 2; kk++) {
            wmma::fragment<wmma::matrix_a,16,16,16,__nv_bfloat16,wmma::row_major> af[2];
            wmma::fragment<wmma::matrix_b,16,16,16,__nv_bfloat16,wmma::col_major> bf[2];
            #pragma unroll
            for (int i = 0; i < 2; i++)
                wmma::load_matrix_sync(af[i], &Qa[bb][wm*32 + i*16][kk*16], 40);
            #pragma unroll
            for (int j = 0; j < 2; j++)
                wmma::load_matrix_sync(bf[j], &Ks[bb][wn*32 + j*16][kk*16], 40);
            #pragma unroll
            for (int i = 0; i < 2; i++)
                #pragma unroll
                for (int j = 0; j < 2; j++)
                    wmma::mma_sync(acc[i][j], af[i], bf[j], acc[i][j]);
        }
        __syncthreads();
    }
    #undef S1_STAGE

    float* outb = g_S1 + (size_t)b*NA*NT;
    #pragma unroll
    for (int i = 0; i < 2; i++)
        #pragma unroll
        for (int j = 0; j < 2; j++) {
            wmma::store_matrix_sync(&epi[w][0][0], acc[i][j], 16, wmma::mem_row_major);
            __syncwarp();
            #pragma unroll
            for (int e = 0; e < 2; e++) {
                int idx2 = lane + e*32;
                int r = idx2 >> 2, c4 = (idx2 & 3) * 4;
                int ga = wm*32 + i*16 + r;
                int gt = col0 + wn*32 + j*16 + c4;
                *(float4*)(outb + (size_t)ga*NT + gt) = *(float4*)(&epi[w][r][c4]);
            }
            __syncwarp();
        }
}

// ---------------- stage-1 softmax over N=4096 -------------------------------
__global__ void softmax1() {
    int row = blockIdx.x;
    const float* s = g_S1 + (size_t)row*NT;
    __nv_bfloat16* p = g_P1 + (size_t)row*NT;
    int t = threadIdx.x;
    __shared__ float red[8];

    float m = -1e30f;
    for (int i = t; i < NT; i += 256) m = fmaxf(m, s[i]);
    #pragma unroll
    for (int o = 16; o; o >>= 1) m = fmaxf(m, __shfl_xor_sync(0xffffffffu, m, o));
    if ((t & 31) == 0) red[t >> 5] = m;
    __syncthreads();
    float gm = red[0];
    #pragma unroll
    for (int i = 1; i < 8; i++) gm = fmaxf(gm, red[i]);
    __syncthreads();

    float sum = 0.f;
    for (int i = t; i < NT; i += 256) sum += __expf(s[i] - gm);
    #pragma unroll
    for (int o = 16; o; o >>= 1) sum += __shfl_xor_sync(0xffffffffu, sum, o);
    if ((t & 31) == 0) red[t >> 5] = sum;
    __syncthreads();
    float gs = 0.f;
    #pragma unroll
    for (int i = 0; i < 8; i++) gs += red[i];
    float inv = 1.f / gs;
    for (int i = t; i < NT; i += 256)
        p[i] = __float2bfloat16(__expf(s[i] - gm) * inv);
}

// ---------------- va partials: split-K over tokens ---------------------------
// grid (8 splits, 8 batches), 2-stage cp.async, out partial [64,256] per block
__global__ void __launch_bounds__(256) gemm_va0() {
    __shared__ __align__(16) char smva[44032];
    __nv_bfloat16 (*Ps)[64][40]  = ( __nv_bfloat16(*)[64][40])  smva;          // 2x5120
    __nv_bfloat16 (*Vs)[32][264] = ( __nv_bfloat16(*)[32][264])(smva + 10240); // 2x16896
    float (*epi)[16][16]         = ( float(*)[16][16])          smva;          // reuse Ps
    uint32_t sP = smem_u32(smva), sV = sP + 10240u;

    int split = blockIdx.x, b = blockIdx.y;
    int tok0 = split * 512;
    int tid = threadIdx.x;
    int w = tid >> 5, lane = tid & 31;
    int wm = w >> 2, wn = w & 3;

    wmma::fragment<wmma::accumulator,16,16,16,float> acc[2][4];
    #pragma unroll
    for (int i = 0; i < 2; i++)
        #pragma unroll
        for (int j = 0; j < 4; j++) wmma::fill_fragment(acc[i][j], 0.f);

    #define VA_STAGE(kc, bb) {                                                     \
        {   int pr = tid >> 2, pc = (tid & 3) * 8;                                 \
            CPA16(sP + (uint32_t)(bb)*5120u + (uint32_t)pr*80u + (uint32_t)pc*2u,  \
                  g_P1 + (size_t)b*NA*NT + (size_t)pr*NT + tok0 + (kc) + pc); }    \
        _Pragma("unroll")                                                          \
        for (int r = 0; r < 4; r++) {                                              \
            int idx = tid + r*256;                                                 \
            int vr = idx >> 5, vc = (idx & 31) * 8;                                \
            CPA16(sV + (uint32_t)(bb)*16896u + (uint32_t)vr*528u + (uint32_t)vc*2u,\
                  g_qkv + (size_t)(b*NT + tok0 + (kc) + vr)*QKVLD + 2*DD + vc);    \
        }                                                                          \
        CPA_COMMIT(); }

    VA_STAGE(0, 0);
    for (int s = 0; s < 16; s++) {
        if (s < 15) VA_STAGE((s+1)*32, (s+1)&1);
        if (s < 15) { CPA_WAIT(1); } else { CPA_WAIT(0); }
        __syncthreads();
        int bb = s & 1;
        #pragma unroll
        for (int kk = 0; kk < 2; kk++) {
            wmma::fragment<wmma::matrix_a,16,16,16,__nv_bfloat16,wmma::row_major> af[2];
            wmma::fragment<wmma::matrix_b,16,16,16,__nv_bfloat16,wmma::row_major> bf[4];
            #pragma unroll
            for (int i = 0; i < 2; i++)
                wmma::load_matrix_sync(af[i], &Ps[bb][wm*32 + i*16][kk*16], 40);
            #pragma unroll
            for (int j = 0; j < 4; j++)
                wmma::load_matrix_sync(bf[j], &Vs[bb][kk*16][wn*64 + j*16], 264);
            #pragma unroll
            for (int i = 0; i < 2; i++)
                #pragma unroll
                for (int j = 0; j < 4; j++)
                    wmma::mma_sync(acc[i][j], af[i], bf[j], acc[i][j]);
        }
        __syncthreads();
    }
    #undef VA_STAGE

    float* outb = g_vap + (size_t)(b*8 + split)*NA*DD;
    #pragma unroll
    for (int i = 0; i < 2; i++)
        #pragma unroll
        for (int j = 0; j < 4; j++) {
            wmma::store_matrix_sync(&epi[w][0][0], acc[i][j], 16, wmma::mem_row_major);
            __syncwarp();
            #pragma unroll
            for (int e = 0; e < 2; e++) {
                int idx2 = lane + e*32;
                int r = idx2 >> 2, c4 = (idx2 & 3) * 4;
                int ga = wm*32 + i*16 + r;
                int gd = wn*64 + j*16 + c4;
                *(float4*)(outb + (size_t)ga*DD + gd) = *(float4*)(&epi[w][r][c4]);
            }
            __syncwarp();
        }
}

// ---------------- fc1: sum partials, then va = va0 @ W_fc1 + b --------------
__global__ void fc1k(const float* __restrict__ W, const float* __restrict__ bias) {
    __shared__ float r0[DD];
    int row = blockIdx.x;  // b*NA + a
    int b = row >> 6, a = row & 63;
    int i = threadIdx.x;
    float acc = 0.f;
    #pragma unroll
    for (int sp = 0; sp < 8; sp++)
        acc += g_vap[(size_t)(b*8 + sp)*NA*DD + (size_t)a*DD + i];
    r0[i] = acc;
    __syncthreads();
    int o = threadIdx.x;
    float s = bias[o];
    #pragma unroll 8
    for (int d = 0; d < DD; d++) s += r0[d] * W[d*DD + o];
    g_va[(size_t)row*DD + o] = __float2bfloat16(s);
}

// ---------------- stage 2: logits -> softmax(K=64) -> @ va ------------------
// per block: 128 tokens of one batch. Dynamic smem 99328B, cp.async staging.
__global__ void __launch_bounds__(256) stage2() {
    extern __shared__ __align__(16) char sm2[];
    __nv_bfloat16 (*Qs)[128][40] = ( __nv_bfloat16(*)[128][40]) sm2;             // 20480
    __nv_bfloat16 (*Ka)[64][40]  = ( __nv_bfloat16(*)[64][40]) (sm2 + 20480);    // 10240
    float* logits                = ( float*)                   (sm2 + 30720);    // 34816
    __nv_bfloat16 (*Vs)[264]     = ( __nv_bfloat16(*)[264])    (sm2 + 65536);    // 33792
    __nv_bfloat16 (*Pm)[72]      = ( __nv_bfloat16(*)[72])     sm2;              // reuse Qs
    float (*epi)[16][16]         = ( float(*)[16][16])         (sm2 + 20480);    // reuse Ka
    uint32_t sQ = smem_u32(sm2), sKa = sQ + 20480u, sV = sQ + 65536u;

    int b = blockIdx.y, t0 = blockIdx.x * 128;
    int tid = threadIdx.x;
    int w = tid >> 5, lane = tid & 31;

    // async prefetch va tile [64,256] into Vs (own group; drained by phase-A waits)
    #pragma unroll
    for (int r = 0; r < 8; r++) {
        int idx = tid + r*256;
        int vr = idx >> 5, vc = (idx & 31) * 8;
        CPA16(sV + (uint32_t)vr*528u + (uint32_t)vc*2u,
              g_va + (size_t)(b*NA + vr)*DD + vc);
    }
    CPA_COMMIT();

    // --- phase A: logits[128,64] = q_tile @ ka^T, warps 4x2, warp 32x32 ---
    {
        int wm = w >> 1, wn = w & 1;
        wmma::fragment<wmma::accumulator,16,16,16,float> acc[2][2];
        #pragma unroll
        for (int i = 0; i < 2; i++)
            #pragma unroll
            for (int j = 0; j < 2; j++) wmma::fill_fragment(acc[i][j], 0.f);

        #define S2_STAGE(kc, bb) {                                                 \
            _Pragma("unroll")                                                      \
            for (int r = 0; r < 2; r++) {                                          \
                int idx = tid + r*256;                                             \
                int qr = idx >> 2, qc = (idx & 3) * 8;                             \
                CPA16(sQ + (uint32_t)(bb)*10240u + (uint32_t)qr*80u + (uint32_t)qc*2u, \
                      g_qkv + (size_t)(b*NT + t0 + qr)*QKVLD + (kc) + qc);         \
            }                                                                      \
            {   int ar = tid >> 2, ac = (tid & 3) * 8;                             \
                CPA16(sKa + (uint32_t)(bb)*5120u + (uint32_t)ar*80u + (uint32_t)ac*2u, \
                      g_kagent + (size_t)ar*DD + (kc) + ac); }                     \
            CPA_COMMIT(); }

        S2_STAGE(0, 0);
        for (int s = 0; s < 8; s++) {
            if (s < 7) S2_STAGE((s+1)*32, (s+1)&1);
            if (s < 7) { CPA_WAIT(1); } else { CPA_WAIT(0); }
            __syncthreads();
            int bb = s & 1;
            #pragma unroll
            for (int kk = 0; kk < 2; kk++) {
                wmma::fragment<wmma::matrix_a,16,16,16,__nv_bfloat16,wmma::row_major> af[2];
                wmma::fragment<wmma::matrix_b,16,16,16,__nv_bfloat16,wmma::col_major> bf[2];
                #pragma unroll
                for (int i = 0; i < 2; i++)
                    wmma::load_matrix_sync(af[i], &Qs[bb][wm*32 + i*16][kk*16], 40);
                #pragma unroll
                for (int j = 0; j < 2; j++)
                    wmma::load_matrix_sync(bf[j], &Ka[bb][wn*32 + j*16][kk*16], 40);
                #pragma unroll
                for (int i = 0; i < 2; i++)
                    #pragma unroll
                    for (int j = 0; j < 2; j++)
                        wmma::mma_sync(acc[i][j], af[i], bf[j], acc[i][j]);
            }
            __syncthreads();
        }
        #undef S2_STAGE
        #pragma unroll
        for (int i = 0; i < 2; i++)
            #pragma unroll
            for (int j = 0; j < 2; j++)
                wmma::store_matrix_sync(logits + (wm*32 + i*16)*68 + wn*32 + j*16,
                                        acc[i][j], 68, wmma::mem_row_major);
    }
    __syncthreads();

    // --- phase B: per-row softmax over 64 agents -> Pm (bf16, ld 72) ---
    if (tid < 128) {
        const float* lr = logits + tid*68;
        float m = -1e30f;
        #pragma unroll 8
        for (int c = 0; c < 64; c++) m = fmaxf(m, lr[c]);
        float sum = 0.f;
        #pragma unroll 8
        for (int c = 0; c < 64; c++) sum += __expf(lr[c] - m);
        float inv = 1.f / sum;
        #pragma unroll 8
        for (int c = 0; c < 64; c++)
            Pm[tid][c] = __float2bfloat16(__expf(lr[c] - m) * inv);
    }
    __syncthreads();

    // --- phase C: mid[128,256] = Pm[128,64] @ Vs[64,256]; two N passes ---
    {
        int wm = w >> 1, wn = w & 1;
        for (int nc = 0; nc < 2; nc++) {
            wmma::fragment<wmma::accumulator,16,16,16,float> acc[2][4];
            #pragma unroll
            for (int i = 0; i < 2; i++)
                #pragma unroll
                for (int j = 0; j < 4; j++) wmma::fill_fragment(acc[i][j], 0.f);
            #pragma unroll
            for (int kk = 0; kk < 4; kk++) {
                wmma::fragment<wmma::matrix_a,16,16,16,__nv_bfloat16,wmma::row_major> af[2];
                wmma::fragment<wmma::matrix_b,16,16,16,__nv_bfloat16,wmma::row_major> bf[4];
                #pragma unroll
                for (int i = 0; i < 2; i++)
                    wmma::load_matrix_sync(af[i], &Pm[wm*32 + i*16][kk*16], 72);
                #pragma unroll
                for (int j = 0; j < 4; j++)
                    wmma::load_matrix_sync(bf[j], &Vs[kk*16][nc*128 + wn*64 + j*16], 264);
                #pragma unroll
                for (int i = 0; i < 2; i++)
                    #pragma unroll
                    for (int j = 0; j < 4; j++)
                        wmma::mma_sync(acc[i][j], af[i], bf[j], acc[i][j]);
            }
            int r = lane >> 1, c8 = (lane & 1) * 8;
            #pragma unroll
            for (int i = 0; i < 2; i++)
                #pragma unroll
                for (int j = 0; j < 4; j++) {
                    wmma::store_matrix_sync(&epi[w][0][0], acc[i][j], 16, wmma::mem_row_major);
                    __syncwarp();
                    int grow = t0 + wm*32 + i*16 + r;
                    int gcol = nc*128 + wn*64 + j*16 + c8;
                    __nv_bfloat16 tmp[8];
                    #pragma unroll
                    for (int e = 0; e < 8; e++)
                        tmp[e] = __float2bfloat16(epi[w][r][c8+e]);
                    *(uint4*)(g_mid + (size_t)(b*NT + grow)*DD + gcol) = *(uint4*)tmp;
                    __syncwarp();
                }
        }
    }
}

// ---------------- fc2 + bias + residual -> out ------------------------------
// tile 128x128, BK=32, 3-stage cp.async, f32 out with residual
__global__ void __launch_bounds__(256) gemm_fc2(const float* __restrict__ bias,
                                                const float* __restrict__ x,
                                                float* __restrict__ out) {
    extern __shared__ __align__(16) char smf[];
    __nv_bfloat16 (*As)[128][40] = (__nv_bfloat16(*)[128][40]) smf;
    __nv_bfloat16 (*Bs)[32][136] = (__nv_bfloat16(*)[32][136])(smf + 30720);
    float (*epi)[16][16]         = (float(*)[16][16])          smf;
    uint32_t sA = smem_u32(smf), sB = sA + 30720u;

    int tid = threadIdx.x;
    int w = tid >> 5, lane = tid & 31;
    int wm = w >> 2, wn = w & 3;
    int row0 = blockIdx.y * 128, col0 = blockIdx.x * 128;

    wmma::fragment<wmma::accumulator,16,16,16,float> acc[4][2];
    #pragma unroll
    for (int i = 0; i < 4; i++)
        #pragma unroll
        for (int j = 0; j < 2; j++) wmma::fill_fragment(acc[i][j], 0.f);

    #define FC2_STAGE(kc, bb) {                                                    \
        _Pragma("unroll")                                                          \
        for (int r = 0; r < 2; r++) {                                              \
            int idx = tid + r*256;                                                 \
            int ar = idx >> 2, ac = (idx & 3) * 8;                                 \
            CPA16(sA + (uint32_t)(bb)*10240u + (uint32_t)ar*80u + (uint32_t)ac*2u, \
                  g_mid + (size_t)(row0+ar)*DD + (kc) + ac);                       \
        }                                                                          \
        _Pragma("unroll")                                                          \
        for (int r = 0; r < 2; r++) {                                              \
            int idx = tid + r*256;                                                 \
            int br = idx >> 4, bc = (idx & 15) * 8;                                \
            CPA16(sB + (uint32_t)(bb)*8704u + (uint32_t)br*272u + (uint32_t)bc*2u, \
                  g_Wfc2 + (size_t)((kc)+br)*DD + col0 + bc);                      \
        }                                                                          \
        CPA_COMMIT(); }

    FC2_STAGE(0, 0);
    FC2_STAGE(32, 1);
    for (int s = 0; s < 8; s++) {
        if (s < 6) FC2_STAGE((s+2)*32, (s+2)%3);
        if (s < 6)      { CPA_WAIT(2); }
        else if (s == 6){ CPA_WAIT(1); }
        else            { CPA_WAIT(0); }
        __syncthreads();
        int bb = s % 3;
        #pragma unroll
        for (int kk = 0; kk < 2; kk++) {
            wmma::fragment<wmma::matrix_a,16,16,16,__nv_bfloat16,wmma::row_major> af[4];
            wmma::fragment<wmma::matrix_b,16,16,16,__nv_bfloat16,wmma::row_major> bf[2];
            #pragma unroll
            for (int i = 0; i < 4; i++)
                wmma::load_matrix_sync(af[i], &As[bb][wm*64 + i*16][kk*16], 40);
            #pragma unroll
            for (int j = 0; j < 2; j++)
                wmma::load_matrix_sync(bf[j], &Bs[bb][kk*16][wn*32 + j*16], 136);
            #pragma unroll
            for (int i = 0; i < 4; i++)
                #pragma unroll
                for (int j = 0; j < 2; j++)
                    wmma::mma_sync(acc[i][j], af[i], bf[j], acc[i][j]);
        }
        __syncthreads();
    }
    #undef FC2_STAGE

    int r = lane >> 1, c8 = (lane & 1) * 8;
    #pragma unroll
    for (int i = 0; i < 4; i++)
        #pragma unroll
        for (int j = 0; j < 2; j++) {
            wmma::store_matrix_sync(&epi[w][0][0], acc[i][j], 16, wmma::mem_row_major);
            __syncwarp();
            int gr = row0 + wm*64 + i*16 + r;
            int gc = col0 + wn*32 + j*16 + c8;
            size_t gi = (size_t)gr*DD + gc;
            float o0[4], o1[4];
            #pragma unroll
            for (int e = 0; e < 4; e++) o0[e] = epi[w][r][c8+e]   + bias[gc+e]   + x[gi+e];
            #pragma unroll
            for (int e = 0; e < 4; e++) o1[e] = epi[w][r][c8+4+e] + bias[gc+4+e] + x[gi+4+e];
            *(float4*)(out + gi)     = *(float4*)o0;
            *(float4*)(out + gi + 4) = *(float4*)o1;
            __syncwarp();
        }
}

// ---------------- launcher ---------------------------------------------------
#define BIG_SMEM 56832

extern "C" void kernel_launch(void* const* d_in, const int* in_sizes, int n_in,
                              void* d_out, int out_size) {
    const float* agent = (const float*)d_in[0];
    const float* x     = (const float*)d_in[1];
    const float* Wqkv  = (const float*)d_in[2];
    const float* bqkv  = (const float*)d_in[3];
    const float* Wag   = (const float*)d_in[4];
    const float* bag   = (const float*)d_in[5];
    const float* Wfc1  = (const float*)d_in[6];
    const float* bfc1  = (const float*)d_in[7];
    const float* Wfc2  = (const float*)d_in[8];
    const float* bfc2  = (const float*)d_in[9];
    float* out = (float*)d_out;

    cudaFuncSetAttribute(stage2,   cudaFuncAttributeMaxDynamicSharedMemorySize, 99328);
    cudaFuncSetAttribute(gemm_qkv, cudaFuncAttributeMaxDynamicSharedMemorySize, BIG_SMEM);
    cudaFuncSetAttribute(gemm_fc2, cudaFuncAttributeMaxDynamicSharedMemorySize, BIG_SMEM);

    conv_inputs<<<2048, 256>>>(x, Wqkv, Wfc2);
    agent_proj<<<64, 512>>>(agent, Wag, bag);
    gemm_qkv<<<dim3(6, 256), 256, BIG_SMEM>>>(bqkv);
    gemm_s1<<<dim3(32, 8), 256>>>();
    softmax1<<<512, 256>>>();
    gemm_va0<<<dim3(8, 8), 256>>>();
    fc1k<<<512, 256>>>(Wfc1, bfc1);
    stage2<<<dim3(32, 8), 256, 99328>>>();
    gemm_fc2<<<dim3(2, 256), 256, BIG_SMEM>>>(bfc2, x, out);
}

// round 5
// speedup vs baseline: 2.9997x; 1.0708x over previous
#include <cuda_runtime.h>
#include <cuda_bf16.h>
#include <mma.h>
#include <cstdint>

using namespace nvcuda;

#define NB 8
#define NT 4096
#define NA 64
#define DD 256
#define MTOK (NB*NT)
#define QKVLD 768

// ---------------- scratch (device globals; no allocations allowed) ----------
__device__ __nv_bfloat16 g_xb[MTOK*DD];              // x in bf16
__device__ __nv_bfloat16 g_Wqkv[DD*3*DD];            // W_qkv bf16 [K,N]
__device__ __nv_bfloat16 g_Wfc2[DD*DD];              // W_fc2 bf16 [K,N]
__device__ __nv_bfloat16 g_qkv[(size_t)MTOK*3*DD];   // q|k|v per token, bf16
__device__ __nv_bfloat16 g_qagent[NA*DD];            // scale folded in
__device__ __nv_bfloat16 g_kagent[NA*DD];            // scale folded in
__device__ float        g_S1[NB*NA*NT];              // stage-1 logits
__device__ __nv_bfloat16 g_P1[NB*NA*NT];             // stage-1 probs
__device__ float        g_vap[NB*8*NA*DD];           // split-K partials of attn1@v
__device__ __nv_bfloat16 g_va[NB*NA*DD];             // after fc1, bf16
__device__ __nv_bfloat16 g_mid[MTOK*DD];             // attn2 @ va, bf16

// ---------------- cp.async helpers ------------------------------------------
__device__ __forceinline__ uint32_t smem_u32(const void* p) {
    uint32_t a;
    asm("{ .reg .u64 t; cvta.to.shared.u64 t, %1; cvt.u32.u64 %0, t; }" : "=r"(a) : "l"(p));
    return a;
}
#define CPA16(s, g)  asm volatile("cp.async.cg.shared.global [%0], [%1], 16;" :: "r"(s), "l"(g))
#define CPA_COMMIT() asm volatile("cp.async.commit_group;" ::: "memory")
#define CPA_WAIT(n)  asm volatile("cp.async.wait_group %0;" :: "n"(n) : "memory")

// ---------------- input conversion ------------------------------------------
__global__ void conv_inputs(const float* __restrict__ x,
                            const float* __restrict__ Wqkv,
                            const float* __restrict__ Wfc2) {
    int stride = gridDim.x * blockDim.x;
    int tid = blockIdx.x * blockDim.x + threadIdx.x;
    for (int i = tid; i < (MTOK*DD)/4; i += stride) {
        float4 v = *(const float4*)(x + i*4);
        __nv_bfloat16 t[4] = {__float2bfloat16(v.x), __float2bfloat16(v.y),
                              __float2bfloat16(v.z), __float2bfloat16(v.w)};
        *(uint2*)(g_xb + i*4) = *(uint2*)t;
    }
    for (int i = tid; i < DD*3*DD; i += stride)
        g_Wqkv[i] = __float2bfloat16(Wqkv[i]);
    for (int i = tid; i < DD*DD; i += stride)
        g_Wfc2[i] = __float2bfloat16(Wfc2[i]);
}

// ---------------- agent projection (tiny) -----------------------------------
__global__ void agent_proj(const float* __restrict__ agent,
                           const float* __restrict__ W,
                           const float* __restrict__ b) {
    __shared__ float arow[DD];
    int a = blockIdx.x;
    for (int i = threadIdx.x; i < DD; i += blockDim.x)
        arow[i] = agent[a*DD + i];
    __syncthreads();
    int o = threadIdx.x;  // 0..511
    float s = 0.f;
    #pragma unroll 8
    for (int d = 0; d < DD; d++)
        s += arow[d] * W[d*2*DD + o];
    s += b[o];
    s *= 0.0625f;  // 256^-0.5
    if (o < DD) g_qagent[a*DD + o]      = __float2bfloat16(s);
    else        g_kagent[a*DD + (o-DD)] = __float2bfloat16(s);
}

// ---------------- qkv GEMM: [32768,256] @ [256,768] + b --------------------
// tile 128x128, BK=64, 2-stage, 4 warps (2x2), warp 64x64, one sync/iter
// dyn smem: A 2x18432 | B 2x17408 = 71680; epilogue reuses A region
__global__ void __launch_bounds__(128) gemm_qkv(const float* __restrict__ bqkv) {
    extern __shared__ __align__(16) char smq[];
    __nv_bfloat16 (*As)[128][72] = (__nv_bfloat16(*)[128][72]) smq;
    __nv_bfloat16 (*Bs)[64][136] = (__nv_bfloat16(*)[64][136])(smq + 36864);
    float (*epi)[16][16]         = (float(*)[16][16])          smq;
    uint32_t sA = smem_u32(smq), sB = sA + 36864u;

    int tid = threadIdx.x;
    int w = tid >> 5, lane = tid & 31;
    int wm = w >> 1, wn = w & 1;
    int row0 = blockIdx.y * 128, col0 = blockIdx.x * 128;

    wmma::fragment<wmma::accumulator,16,16,16,float> acc[4][4];
    #pragma unroll
    for (int i = 0; i < 4; i++)
        #pragma unroll
        for (int j = 0; j < 4; j++) wmma::fill_fragment(acc[i][j], 0.f);

    #define QKV_STAGE(kc, bb) {                                                    \
        _Pragma("unroll")                                                          \
        for (int r = 0; r < 8; r++) {                                              \
            int idx = tid + r*128;                                                 \
            int ar = idx >> 3, ac = (idx & 7) * 8;                                 \
            CPA16(sA + (uint32_t)(bb)*18432u + (uint32_t)ar*144u + (uint32_t)ac*2u,\
                  g_xb + (size_t)(row0+ar)*DD + (kc) + ac);                        \
        }                                                                          \
        _Pragma("unroll")                                                          \
        for (int r = 0; r < 8; r++) {                                              \
            int idx = tid + r*128;                                                 \
            int br = idx >> 4, bc = (idx & 15) * 8;                                \
            CPA16(sB + (uint32_t)(bb)*17408u + (uint32_t)br*272u + (uint32_t)bc*2u,\
                  g_Wqkv + (size_t)((kc)+br)*QKVLD + col0 + bc);                   \
        }                                                                          \
        CPA_COMMIT(); }

    QKV_STAGE(0, 0);
    for (int s = 0; s < 4; s++) {
        CPA_WAIT(0);
        __syncthreads();
        if (s < 3) QKV_STAGE((s+1)*64, (s+1)&1);
        int bb = s & 1;
        #pragma unroll
        for (int k4 = 0; k4 < 4; k4++) {
            wmma::fragment<wmma::matrix_a,16,16,16,__nv_bfloat16,wmma::row_major> af[4];
            wmma::fragment<wmma::matrix_b,16,16,16,__nv_bfloat16,wmma::row_major> bf[4];
            #pragma unroll
            for (int i = 0; i < 4; i++)
                wmma::load_matrix_sync(af[i], &As[bb][wm*64 + i*16][k4*16], 72);
            #pragma unroll
            for (int j = 0; j < 4; j++)
                wmma::load_matrix_sync(bf[j], &Bs[bb][k4*16][wn*64 + j*16], 136);
            #pragma unroll
            for (int i = 0; i < 4; i++)
                #pragma unroll
                for (int j = 0; j < 4; j++)
                    wmma::mma_sync(acc[i][j], af[i], bf[j], acc[i][j]);
        }
    }
    #undef QKV_STAGE
    __syncthreads();

    int r = lane >> 1, c8 = (lane & 1) * 8;
    #pragma unroll
    for (int i = 0; i < 4; i++)
        #pragma unroll
        for (int j = 0; j < 4; j++) {
            wmma::store_matrix_sync(&epi[w][0][0], acc[i][j], 16, wmma::mem_row_major);
            __syncwarp();
            int gr = row0 + wm*64 + i*16 + r;
            int gc = col0 + wn*64 + j*16 + c8;
            __nv_bfloat16 tmp[8];
            #pragma unroll
            for (int e = 0; e < 8; e++)
                tmp[e] = __float2bfloat16(epi[w][r][c8+e] + bqkv[gc+e]);
            *(uint4*)(g_qkv + (size_t)gr*QKVLD + gc) = *(uint4*)tmp;
            __syncwarp();
        }
}

// ---------------- stage-1 logits: S1[b] = q_agent @ k_b^T ------------------
// tile 64x128, BK=32, 2-stage cp.async, one sync/iter, 8 warps (2x4)
__global__ void __launch_bounds__(256) gemm_s1() {
    __shared__ __nv_bfloat16 Qa[2][64][40];
    __shared__ __nv_bfloat16 Ks[2][128][40];
    __shared__ float epi[8][16][16];
    uint32_t sQ = smem_u32(&Qa[0][0][0]);
    uint32_t sK = smem_u32(&Ks[0][0][0]);

    int b = blockIdx.y;
    int col0 = blockIdx.x * 128;
    int tid = threadIdx.x;
    int w = tid >> 5, lane = tid & 31;
    int wm = w >> 2, wn = w & 3;

    wmma::fragment<wmma::accumulator,16,16,16,float> acc[2][2];
    #pragma unroll
    for (int i = 0; i < 2; i++)
        #pragma unroll
        for (int j = 0; j < 2; j++) wmma::fill_fragment(acc[i][j], 0.f);

    #define S1_STAGE(kc, bb) {                                                     \
        {   int ar = tid >> 2, ac = (tid & 3) * 8;                                 \
            CPA16(sQ + (uint32_t)(bb)*5120u + (uint32_t)ar*80u + (uint32_t)ac*2u,  \
                  g_qagent + (size_t)ar*DD + (kc) + ac); }                         \
        _Pragma("unroll")                                                          \
        for (int r = 0; r < 2; r++) {                                              \
            int idx = tid + r*256;                                                 \
            int kr = idx >> 2, kcc = (idx & 3) * 8;                                \
            CPA16(sK + (uint32_t)(bb)*10240u + (uint32_t)kr*80u + (uint32_t)kcc*2u,\
                  g_qkv + (size_t)(b*NT + col0 + kr)*QKVLD + DD + (kc) + kcc);     \
        }                                                                          \
        CPA_COMMIT(); }

    S1_STAGE(0, 0);
    for (int s = 0; s < 8; s++) {
        CPA_WAIT(0);
        __syncthreads();
        if (s < 7) S1_STAGE((s+1)*32, (s+1)&1);
        int bb = s & 1;
        #pragma unroll
        for (int kk = 0; kk < 2; kk++) {
            wmma::fragment<wmma::matrix_a,16,16,16,__nv_bfloat16,wmma::row_major> af[2];
            wmma::fragment<wmma::matrix_b,16,16,16,__nv_bfloat16,wmma::col_major> bf[2];
            #pragma unroll
            for (int i = 0; i < 2; i++)
                wmma::load_matrix_sync(af[i], &Qa[bb][wm*32 + i*16][kk*16], 40);
            #pragma unroll
            for (int j = 0; j < 2; j++)
                wmma::load_matrix_sync(bf[j], &Ks[bb][wn*32 + j*16][kk*16], 40);
            #pragma unroll
            for (int i = 0; i < 2; i++)
                #pragma unroll
                for (int j = 0; j < 2; j++)
                    wmma::mma_sync(acc[i][j], af[i], bf[j], acc[i][j]);
        }
    }
    #undef S1_STAGE

    float* outb = g_S1 + (size_t)b*NA*NT;
    #pragma unroll
    for (int i = 0; i < 2; i++)
        #pragma unroll
        for (int j = 0; j < 2; j++) {
            wmma::store_matrix_sync(&epi[w][0][0], acc[i][j], 16, wmma::mem_row_major);
            __syncwarp();
            #pragma unroll
            for (int e = 0; e < 2; e++) {
                int idx2 = lane + e*32;
                int r = idx2 >> 2, c4 = (idx2 & 3) * 4;
                int ga = wm*32 + i*16 + r;
                int gt = col0 + wn*32 + j*16 + c4;
                *(float4*)(outb + (size_t)ga*NT + gt) = *(float4*)(&epi[w][r][c4]);
            }
            __syncwarp();
        }
}

// ---------------- stage-1 softmax over N=4096 (smem row cache) --------------
__global__ void softmax1() {
    __shared__ float rowc[NT];
    __shared__ float red[8];
    int row = blockIdx.x;
    const float* s = g_S1 + (size_t)row*NT;
    __nv_bfloat16* p = g_P1 + (size_t)row*NT;
    int t = threadIdx.x;

    float m = -1e30f;
    for (int i = t; i < NT/4; i += 256) {
        float4 v = *(const float4*)(s + i*4);
        *(float4*)(rowc + i*4) = v;
        m = fmaxf(fmaxf(m, fmaxf(v.x, v.y)), fmaxf(v.z, v.w));
    }
    #pragma unroll
    for (int o = 16; o; o >>= 1) m = fmaxf(m, __shfl_xor_sync(0xffffffffu, m, o));
    if ((t & 31) == 0) red[t >> 5] = m;
    __syncthreads();
    float gm = red[0];
    #pragma unroll
    for (int i = 1; i < 8; i++) gm = fmaxf(gm, red[i]);
    __syncthreads();

    float sum = 0.f;
    for (int i = t; i < NT; i += 256) sum += __expf(rowc[i] - gm);
    #pragma unroll
    for (int o = 16; o; o >>= 1) sum += __shfl_xor_sync(0xffffffffu, sum, o);
    if ((t & 31) == 0) red[t >> 5] = sum;
    __syncthreads();
    float gs = 0.f;
    #pragma unroll
    for (int i = 0; i < 8; i++) gs += red[i];
    float inv = 1.f / gs;
    for (int i = t; i < NT/4; i += 256) {
        float4 v = *(const float4*)(rowc + i*4);
        __nv_bfloat16 t4[4] = {
            __float2bfloat16(__expf(v.x - gm) * inv),
            __float2bfloat16(__expf(v.y - gm) * inv),
            __float2bfloat16(__expf(v.z - gm) * inv),
            __float2bfloat16(__expf(v.w - gm) * inv)};
        *(uint2*)(p + i*4) = *(uint2*)t4;
    }
}

// ---------------- va partials: split-K over tokens ---------------------------
// grid (8 splits, 8 batches), 2-stage cp.async, one sync/iter
__global__ void __launch_bounds__(256) gemm_va0() {
    __shared__ __align__(16) char smva[44032];
    __nv_bfloat16 (*Ps)[64][40]  = ( __nv_bfloat16(*)[64][40])  smva;          // 2x5120
    __nv_bfloat16 (*Vs)[32][264] = ( __nv_bfloat16(*)[32][264])(smva + 10240); // 2x16896
    float (*epi)[16][16]         = ( float(*)[16][16])          smva;          // reuse Ps
    uint32_t sP = smem_u32(smva), sV = sP + 10240u;

    int split = blockIdx.x, b = blockIdx.y;
    int tok0 = split * 512;
    int tid = threadIdx.x;
    int w = tid >> 5, lane = tid & 31;
    int wm = w >> 2, wn = w & 3;

    wmma::fragment<wmma::accumulator,16,16,16,float> acc[2][4];
    #pragma unroll
    for (int i = 0; i < 2; i++)
        #pragma unroll
        for (int j = 0; j < 4; j++) wmma::fill_fragment(acc[i][j], 0.f);

    #define VA_STAGE(kc, bb) {                                                     \
        {   int pr = tid >> 2, pc = (tid & 3) * 8;                                 \
            CPA16(sP + (uint32_t)(bb)*5120u + (uint32_t)pr*80u + (uint32_t)pc*2u,  \
                  g_P1 + (size_t)b*NA*NT + (size_t)pr*NT + tok0 + (kc) + pc); }    \
        _Pragma("unroll")                                                          \
        for (int r = 0; r < 4; r++) {                                              \
            int idx = tid + r*256;                                                 \
            int vr = idx >> 5, vc = (idx & 31) * 8;                                \
            CPA16(sV + (uint32_t)(bb)*16896u + (uint32_t)vr*528u + (uint32_t)vc*2u,\
                  g_qkv + (size_t)(b*NT + tok0 + (kc) + vr)*QKVLD + 2*DD + vc);    \
        }                                                                          \
        CPA_COMMIT(); }

    VA_STAGE(0, 0);
    for (int s = 0; s < 16; s++) {
        CPA_WAIT(0);
        __syncthreads();
        if (s < 15) VA_STAGE((s+1)*32, (s+1)&1);
        int bb = s & 1;
        #pragma unroll
        for (int kk = 0; kk < 2; kk++) {
            wmma::fragment<wmma::matrix_a,16,16,16,__nv_bfloat16,wmma::row_major> af[2];
            wmma::fragment<wmma::matrix_b,16,16,16,__nv_bfloat16,wmma::row_major> bf[4];
            #pragma unroll
            for (int i = 0; i < 2; i++)
                wmma::load_matrix_sync(af[i], &Ps[bb][wm*32 + i*16][kk*16], 40);
            #pragma unroll
            for (int j = 0; j < 4; j++)
                wmma::load_matrix_sync(bf[j], &Vs[bb][kk*16][wn*64 + j*16], 264);
            #pragma unroll
            for (int i = 0; i < 2; i++)
                #pragma unroll
                for (int j = 0; j < 4; j++)
                    wmma::mma_sync(acc[i][j], af[i], bf[j], acc[i][j]);
        }
    }
    #undef VA_STAGE
    __syncthreads();

    float* outb = g_vap + (size_t)(b*8 + split)*NA*DD;
    #pragma unroll
    for (int i = 0; i < 2; i++)
        #pragma unroll
        for (int j = 0; j < 4; j++) {
            wmma::store_matrix_sync(&epi[w][0][0], acc[i][j], 16, wmma::mem_row_major);
            __syncwarp();
            #pragma unroll
            for (int e = 0; e < 2; e++) {
                int idx2 = lane + e*32;
                int r = idx2 >> 2, c4 = (idx2 & 3) * 4;
                int ga = wm*32 + i*16 + r;
                int gd = wn*64 + j*16 + c4;
                *(float4*)(outb + (size_t)ga*DD + gd) = *(float4*)(&epi[w][r][c4]);
            }
            __syncwarp();
        }
}

// ---------------- fc1: sum partials, then va = va0 @ W_fc1 + b --------------
__global__ void fc1k(const float* __restrict__ W, const float* __restrict__ bias) {
    __shared__ float r0[DD];
    int row = blockIdx.x;  // b*NA + a
    int b = row >> 6, a = row & 63;
    int i = threadIdx.x;
    float acc = 0.f;
    #pragma unroll
    for (int sp = 0; sp < 8; sp++)
        acc += g_vap[(size_t)(b*8 + sp)*NA*DD + (size_t)a*DD + i];
    r0[i] = acc;
    __syncthreads();
    int o = threadIdx.x;
    float s = bias[o];
    #pragma unroll 8
    for (int d = 0; d < DD; d++) s += r0[d] * W[d*DD + o];
    g_va[(size_t)row*DD + o] = __float2bfloat16(s);
}

// ---------------- stage 2: logits -> softmax(K=64) -> @ va ------------------
// per block: 128 tokens of one batch. Dynamic smem 99328B, cp.async staging.
__global__ void __launch_bounds__(256) stage2() {
    extern __shared__ __align__(16) char sm2[];
    __nv_bfloat16 (*Qs)[128][40] = ( __nv_bfloat16(*)[128][40]) sm2;             // 20480
    __nv_bfloat16 (*Ka)[64][40]  = ( __nv_bfloat16(*)[64][40]) (sm2 + 20480);    // 10240
    float* logits                = ( float*)                   (sm2 + 30720);    // 34816
    __nv_bfloat16 (*Vs)[264]     = ( __nv_bfloat16(*)[264])    (sm2 + 65536);    // 33792
    __nv_bfloat16 (*Pm)[72]      = ( __nv_bfloat16(*)[72])     sm2;              // reuse Qs
    float (*epi)[16][16]         = ( float(*)[16][16])         (sm2 + 20480);    // reuse Ka
    uint32_t sQ = smem_u32(sm2), sKa = sQ + 20480u, sV = sQ + 65536u;

    int b = blockIdx.y, t0 = blockIdx.x * 128;
    int tid = threadIdx.x;
    int w = tid >> 5, lane = tid & 31;

    // async prefetch va tile [64,256] into Vs
    #pragma unroll
    for (int r = 0; r < 8; r++) {
        int idx = tid + r*256;
        int vr = idx >> 5, vc = (idx & 31) * 8;
        CPA16(sV + (uint32_t)vr*528u + (uint32_t)vc*2u,
              g_va + (size_t)(b*NA + vr)*DD + vc);
    }
    CPA_COMMIT();

    // --- phase A: logits[128,64] = q_tile @ ka^T, warps 4x2, warp 32x32 ---
    {
        int wm = w >> 1, wn = w & 1;
        wmma::fragment<wmma::accumulator,16,16,16,float> acc[2][2];
        #pragma unroll
        for (int i = 0; i < 2; i++)
            #pragma unroll
            for (int j = 0; j < 2; j++) wmma::fill_fragment(acc[i][j], 0.f);

        #define S2_STAGE(kc, bb) {                                                 \
            _Pragma("unroll")                                                      \
            for (int r = 0; r < 2; r++) {                                          \
                int idx = tid + r*256;                                             \
                int qr = idx >> 2, qc = (idx & 3) * 8;                             \
                CPA16(sQ + (uint32_t)(bb)*10240u + (uint32_t)qr*80u + (uint32_t)qc*2u, \
                      g_qkv + (size_t)(b*NT + t0 + qr)*QKVLD + (kc) + qc);         \
            }                                                                      \
            {   int ar = tid >> 2, ac = (tid & 3) * 8;                             \
                CPA16(sKa + (uint32_t)(bb)*5120u + (uint32_t)ar*80u + (uint32_t)ac*2u, \
                      g_kagent + (size_t)ar*DD + (kc) + ac); }                     \
            CPA_COMMIT(); }

        S2_STAGE(0, 0);
        for (int s = 0; s < 8; s++) {
            CPA_WAIT(0);
            __syncthreads();
            if (s < 7) S2_STAGE((s+1)*32, (s+1)&1);
            int bb = s & 1;
            #pragma unroll
            for (int kk = 0; kk < 2; kk++) {
                wmma::fragment<wmma::matrix_a,16,16,16,__nv_bfloat16,wmma::row_major> af[2];
                wmma::fragment<wmma::matrix_b,16,16,16,__nv_bfloat16,wmma::col_major> bf[2];
                #pragma unroll
                for (int i = 0; i < 2; i++)
                    wmma::load_matrix_sync(af[i], &Qs[bb][wm*32 + i*16][kk*16], 40);
                #pragma unroll
                for (int j = 0; j < 2; j++)
                    wmma::load_matrix_sync(bf[j], &Ka[bb][wn*32 + j*16][kk*16], 40);
                #pragma unroll
                for (int i = 0; i < 2; i++)
                    #pragma unroll
                    for (int j = 0; j < 2; j++)
                        wmma::mma_sync(acc[i][j], af[i], bf[j], acc[i][j]);
            }
        }
        #undef S2_STAGE
        __syncthreads();
        #pragma unroll
        for (int i = 0; i < 2; i++)
            #pragma unroll
            for (int j = 0; j < 2; j++)
                wmma::store_matrix_sync(logits + (wm*32 + i*16)*68 + wn*32 + j*16,
                                        acc[i][j], 68, wmma::mem_row_major);
    }
    __syncthreads();

    // --- phase B: per-row softmax over 64 agents -> Pm (bf16, ld 72) ---
    if (tid < 128) {
        const float* lr = logits + tid*68;
        float m = -1e30f;
        #pragma unroll 8
        for (int c = 0; c < 64; c++) m = fmaxf(m, lr[c]);
        float sum = 0.f;
        #pragma unroll 8
        for (int c = 0; c < 64; c++) sum += __expf(lr[c] - m);
        float inv = 1.f / sum;
        #pragma unroll 8
        for (int c = 0; c < 64; c++)
            Pm[tid][c] = __float2bfloat16(__expf(lr[c] - m) * inv);
    }
    __syncthreads();

    // --- phase C: mid[128,256] = Pm[128,64] @ Vs[64,256]; two N passes ---
    {
        int wm = w >> 1, wn = w & 1;
        for (int nc = 0; nc < 2; nc++) {
            wmma::fragment<wmma::accumulator,16,16,16,float> acc[2][4];
            #pragma unroll
            for (int i = 0; i < 2; i++)
                #pragma unroll
                for (int j = 0; j < 4; j++) wmma::fill_fragment(acc[i][j], 0.f);
            #pragma unroll
            for (int kk = 0; kk < 4; kk++) {
                wmma::fragment<wmma::matrix_a,16,16,16,__nv_bfloat16,wmma::row_major> af[2];
                wmma::fragment<wmma::matrix_b,16,16,16,__nv_bfloat16,wmma::row_major> bf[4];
                #pragma unroll
                for (int i = 0; i < 2; i++)
                    wmma::load_matrix_sync(af[i], &Pm[wm*32 + i*16][kk*16], 72);
                #pragma unroll
                for (int j = 0; j < 4; j++)
                    wmma::load_matrix_sync(bf[j], &Vs[kk*16][nc*128 + wn*64 + j*16], 264);
                #pragma unroll
                for (int i = 0; i < 2; i++)
                    #pragma unroll
                    for (int j = 0; j < 4; j++)
                        wmma::mma_sync(acc[i][j], af[i], bf[j], acc[i][j]);
            }
            int r = lane >> 1, c8 = (lane & 1) * 8;
            #pragma unroll
            for (int i = 0; i < 2; i++)
                #pragma unroll
                for (int j = 0; j < 4; j++) {
                    wmma::store_matrix_sync(&epi[w][0][0], acc[i][j], 16, wmma::mem_row_major);
                    __syncwarp();
                    int grow = t0 + wm*32 + i*16 + r;
                    int gcol = nc*128 + wn*64 + j*16 + c8;
                    __nv_bfloat16 tmp[8];
                    #pragma unroll
                    for (int e = 0; e < 8; e++)
                        tmp[e] = __float2bfloat16(epi[w][r][c8+e]);
                    *(uint4*)(g_mid + (size_t)(b*NT + grow)*DD + gcol) = *(uint4*)tmp;
                    __syncwarp();
                }
        }
    }
}

// ---------------- fc2 + bias + residual -> out ------------------------------
// tile 128x128, BK=64, 2-stage, 4 warps (2x2), warp 64x64, one sync/iter
__global__ void __launch_bounds__(128) gemm_fc2(const float* __restrict__ bias,
                                                const float* __restrict__ x,
                                                float* __restrict__ out) {
    extern __shared__ __align__(16) char smf[];
    __nv_bfloat16 (*As)[128][72] = (__nv_bfloat16(*)[128][72]) smf;
    __nv_bfloat16 (*Bs)[64][136] = (__nv_bfloat16(*)[64][136])(smf + 36864);
    float (*epi)[16][16]         = (float(*)[16][16])          smf;
    uint32_t sA = smem_u32(smf), sB = sA + 36864u;

    int tid = threadIdx.x;
    int w = tid >> 5, lane = tid & 31;
    int wm = w >> 1, wn = w & 1;
    int row0 = blockIdx.y * 128, col0 = blockIdx.x * 128;

    wmma::fragment<wmma::accumulator,16,16,16,float> acc[4][4];
    #pragma unroll
    for (int i = 0; i < 4; i++)
        #pragma unroll
        for (int j = 0; j < 4; j++) wmma::fill_fragment(acc[i][j], 0.f);

    #define FC2_STAGE(kc, bb) {                                                    \
        _Pragma("unroll")                                                          \
        for (int r = 0; r < 8; r++) {                                              \
            int idx = tid + r*128;                                                 \
            int ar = idx >> 3, ac = (idx & 7) * 8;                                 \
            CPA16(sA + (uint32_t)(bb)*18432u + (uint32_t)ar*144u + (uint32_t)ac*2u,\
                  g_mid + (size_t)(row0+ar)*DD + (kc) + ac);                       \
        }                                                                          \
        _Pragma("unroll")                                                          \
        for (int r = 0; r < 8; r++) {                                              \
            int idx = tid + r*128;                                                 \
            int br = idx >> 4, bc = (idx & 15) * 8;                                \
            CPA16(sB + (uint32_t)(bb)*17408u + (uint32_t)br*272u + (uint32_t)bc*2u,\
                  g_Wfc2 + (size_t)((kc)+br)*DD + col0 + bc);                      \
        }                                                                          \
        CPA_COMMIT(); }

    FC2_STAGE(0, 0);
    for (int s = 0; s < 4; s++) {
        CPA_WAIT(0);
        __syncthreads();
        if (s < 3) FC2_STAGE((s+1)*64, (s+1)&1);
        int bb = s & 1;
        #pragma unroll
        for (int k4 = 0; k4 < 4; k4++) {
            wmma::fragment<wmma::matrix_a,16,16,16,__nv_bfloat16,wmma::row_major> af[4];
            wmma::fragment<wmma::matrix_b,16,16,16,__nv_bfloat16,wmma::row_major> bf[4];
            #pragma unroll
            for (int i = 0; i < 4; i++)
                wmma::load_matrix_sync(af[i], &As[bb][wm*64 + i*16][k4*16], 72);
            #pragma unroll
            for (int j = 0; j < 4; j++)
                wmma::load_matrix_sync(bf[j], &Bs[bb][k4*16][wn*64 + j*16], 136);
            #pragma unroll
            for (int i = 0; i < 4; i++)
                #pragma unroll
                for (int j = 0; j < 4; j++)
                    wmma::mma_sync(acc[i][j], af[i], bf[j], acc[i][j]);
        }
    }
    #undef FC2_STAGE
    __syncthreads();

    int r = lane >> 1, c8 = (lane & 1) * 8;
    #pragma unroll
    for (int i = 0; i < 4; i++)
        #pragma unroll
        for (int j = 0; j < 4; j++) {
            wmma::store_matrix_sync(&epi[w][0][0], acc[i][j], 16, wmma::mem_row_major);
            __syncwarp();
            int gr = row0 + wm*64 + i*16 + r;
            int gc = col0 + wn*64 + j*16 + c8;
            size_t gi = (size_t)gr*DD + gc;
            float o0[4], o1[4];
            #pragma unroll
            for (int e = 0; e < 4; e++) o0[e] = epi[w][r][c8+e]   + bias[gc+e]   + x[gi+e];
            #pragma unroll
            for (int e = 0; e < 4; e++) o1[e] = epi[w][r][c8+4+e] + bias[gc+4+e] + x[gi+4+e];
            *(float4*)(out + gi)     = *(float4*)o0;
            *(float4*)(out + gi + 4) = *(float4*)o1;
            __syncwarp();
        }
}

// ---------------- launcher ---------------------------------------------------
#define BIG_SMEM 71680

extern "C" void kernel_launch(void* const* d_in, const int* in_sizes, int n_in,
                              void* d_out, int out_size) {
    const float* agent = (const float*)d_in[0];
    const float* x     = (const float*)d_in[1];
    const float* Wqkv  = (const float*)d_in[2];
    const float* bqkv  = (const float*)d_in[3];
    const float* Wag   = (const float*)d_in[4];
    const float* bag   = (const float*)d_in[5];
    const float* Wfc1  = (const float*)d_in[6];
    const float* bfc1  = (const float*)d_in[7];
    const float* Wfc2  = (const float*)d_in[8];
    const float* bfc2  = (const float*)d_in[9];
    float* out = (float*)d_out;

    cudaFuncSetAttribute(stage2,   cudaFuncAttributeMaxDynamicSharedMemorySize, 99328);
    cudaFuncSetAttribute(gemm_qkv, cudaFuncAttributeMaxDynamicSharedMemorySize, BIG_SMEM);
    cudaFuncSetAttribute(gemm_fc2, cudaFuncAttributeMaxDynamicSharedMemorySize, BIG_SMEM);

    conv_inputs<<<2048, 256>>>(x, Wqkv, Wfc2);
    agent_proj<<<64, 512>>>(agent, Wag, bag);
    gemm_qkv<<<dim3(6, 256), 128, BIG_SMEM>>>(bqkv);
    gemm_s1<<<dim3(32, 8), 256>>>();
    softmax1<<<512, 256>>>();
    gemm_va0<<<dim3(8, 8), 256>>>();
    fc1k<<<512, 256>>>(Wfc1, bfc1);
    stage2<<<dim3(32, 8), 256, 99328>>>();
    gemm_fc2<<<dim3(2, 256), 128, BIG_SMEM>>>(bfc2, x, out);
}